// round 11
// baseline (speedup 1.0000x reference)
#include <cuda_runtime.h>
#include <cuda_fp16.h>
#include <math.h>
#include <stdint.h>

#define BB 8
#define SEQ 1024
#define HID 1152
#define NHEAD 16
#define HDIM 72
#define DFF 4608
#define MROWS (BB*SEQ)      // 8192
#define MOD6 (6*HID)        // 6912

// ------------------------- scratch (__device__ globals, no allocs) ----------
__device__ float g_mod[BB*MOD6];
__device__ float g_x1[MROWS*HID];
// fp16 activations
__device__ __half g_aih[(size_t)MROWS*HID];
__device__ __half g_qkvh[(size_t)MROWS*3*HID];
__device__ __half g_qh[MROWS*HID];
__device__ __half g_kh[MROWS*HID];
__device__ __half g_vth[MROWS*HID];          // V transposed per head: [b][h][d][SEQ]
__device__ __half g_oh[MROWS*HID];
__device__ __half g_mih[(size_t)MROWS*HID];
__device__ __half g_hh[(size_t)MROWS*DFF];
// transposed fp16 weights  Wt[N][K]
__device__ __half g_wqkt[(size_t)3*HID*HID];
__device__ __half g_wpt[(size_t)HID*HID];
__device__ __half g_wf1t[(size_t)DFF*HID];
__device__ __half g_wf2t[(size_t)HID*DFF];

// ------------------------- helpers ------------------------------------------
__device__ __forceinline__ void cp16(void* smem_dst, const void* gsrc) {
    unsigned s = (unsigned)__cvta_generic_to_shared(smem_dst);
    asm volatile("cp.async.cg.shared.global [%0], [%1], 16;" :: "r"(s), "l"(gsrc));
}
__device__ __forceinline__ void mma_f16(float4& d, const uint32_t* a, const uint32_t* b) {
    asm volatile(
        "mma.sync.aligned.m16n8k16.row.col.f32.f16.f16.f32 "
        "{%0,%1,%2,%3}, {%4,%5,%6,%7}, {%8,%9}, {%0,%1,%2,%3};"
        : "+f"(d.x), "+f"(d.y), "+f"(d.z), "+f"(d.w)
        : "r"(a[0]), "r"(a[1]), "r"(a[2]), "r"(a[3]), "r"(b[0]), "r"(b[1]));
}
__device__ __forceinline__ void mma_f16_k8(float4& d, uint32_t a0, uint32_t a1, uint32_t b0) {
    asm volatile(
        "mma.sync.aligned.m16n8k8.row.col.f32.f16.f16.f32 "
        "{%0,%1,%2,%3}, {%4,%5}, {%6}, {%0,%1,%2,%3};"
        : "+f"(d.x), "+f"(d.y), "+f"(d.z), "+f"(d.w)
        : "r"(a0), "r"(a1), "r"(b0));
}
__device__ __forceinline__ void ldsm4(uint32_t& r0, uint32_t& r1, uint32_t& r2, uint32_t& r3,
                                      uint32_t addr) {
    asm volatile("ldmatrix.sync.aligned.m8n8.x4.shared.b16 {%0,%1,%2,%3}, [%4];"
                 : "=r"(r0), "=r"(r1), "=r"(r2), "=r"(r3) : "r"(addr));
}
__device__ __forceinline__ float fast_gelu(float u) {
    float e = __expf(-1.5957691216057308f * fmaf(0.044715f*u*u, u, u));
    return __fdividef(u, 1.f + e);
}

// ------------------------- weight transpose fp32[K][N] -> fp16[N][K] --------
__global__ void __launch_bounds__(256)
wtrans_kernel(const float* __restrict__ in, __half* __restrict__ out, int K, int N) {
    __shared__ float tile[64][65];
    int k0 = blockIdx.y*64, n0 = blockIdx.x*64;
    int t = threadIdx.x;
    #pragma unroll
    for (int i = 0; i < 4; i++) {
        int idx = t + i*256;
        int r = idx >> 4, c = idx & 15;
        float4 v = *(const float4*)&in[(size_t)(k0 + r)*N + n0 + c*4];
        tile[r][c*4+0] = v.x; tile[r][c*4+1] = v.y;
        tile[r][c*4+2] = v.z; tile[r][c*4+3] = v.w;
    }
    __syncthreads();
    #pragma unroll
    for (int i = 0; i < 8; i++) {
        int idx = t + i*256;
        int n = idx >> 5, c = idx & 31;
        __half2 h = __floats2half2_rn(tile[2*c][n], tile[2*c+1][n]);
        *(__half2*)&out[(size_t)(n0 + n)*K + k0 + 2*c] = h;
    }
}

// ------------------------- fused silu + adaLN (w_ada read ONCE) -------------
__global__ void __launch_bounds__(128)
adaln_kernel(const float* __restrict__ c, const float* __restrict__ w_ada,
             const float* __restrict__ b_ada) {
    __shared__ float sc[BB*HID];   // 36 KB: silu(c) for all 8 batches
    int tid = threadIdx.x;
    for (int i = tid; i < BB*HID; i += 128) {
        float s = c[i];
        sc[i] = s / (1.f + expf(-s));
    }
    __syncthreads();
    int j = blockIdx.x*128 + tid;
    float bj = b_ada[j];
    float acc[BB];
    #pragma unroll
    for (int b = 0; b < BB; b++) acc[b] = bj;
    for (int k = 0; k < HID; k++) {
        float w = w_ada[(size_t)k*MOD6 + j];
        #pragma unroll
        for (int b = 0; b < BB; b++) acc[b] = fmaf(sc[b*HID + k], w, acc[b]);
    }
    #pragma unroll
    for (int b = 0; b < BB; b++) g_mod[b*MOD6 + j] = acc[b];
}

// --------------- fused (optional residual+gate) + LN + modulate -> fp16 -----
__global__ void __launch_bounds__(288)
modulate_kernel(const float* __restrict__ x, const float* __restrict__ res,
                int sh_seg, int sc_seg, int g_seg,
                float* __restrict__ x1_out, __half* __restrict__ mi_out) {
    int r = blockIdx.x, b = r / SEQ, t = threadIdx.x;
    const float* modb = &g_mod[b*MOD6];

    float4 val = *(const float4*)&x[(size_t)r*HID + t*4];
    if (res) {
        float4 rv = *(const float4*)&res[(size_t)r*HID + t*4];
        float4 gv = *(const float4*)&modb[g_seg*HID + t*4];
        val.x = fmaf(gv.x, rv.x, val.x); val.y = fmaf(gv.y, rv.y, val.y);
        val.z = fmaf(gv.z, rv.z, val.z); val.w = fmaf(gv.w, rv.w, val.w);
    }
    if (x1_out) *(float4*)&x1_out[(size_t)r*HID + t*4] = val;

    float s  = val.x + val.y + val.z + val.w;
    float ss = val.x*val.x + val.y*val.y + val.z*val.z + val.w*val.w;
    int lane = t & 31, wid = t >> 5;
    #pragma unroll
    for (int o = 16; o; o >>= 1) {
        s  += __shfl_xor_sync(0xffffffffu, s, o);
        ss += __shfl_xor_sync(0xffffffffu, ss, o);
    }
    __shared__ float sh1[9], sh2[9];
    if (lane == 0) { sh1[wid] = s; sh2[wid] = ss; }
    __syncthreads();
    if (t == 0) {
        float a = 0.f, bb = 0.f;
        #pragma unroll
        for (int i = 0; i < 9; i++) { a += sh1[i]; bb += sh2[i]; }
        sh1[0] = a; sh2[0] = bb;
    }
    __syncthreads();
    float mean = sh1[0] * (1.f/HID);
    float var  = sh2[0] * (1.f/HID) - mean*mean;
    float inv  = rsqrtf(var + 1e-6f);

    float4 sc4 = *(const float4*)&modb[sc_seg*HID + t*4];
    float4 sh4 = *(const float4*)&modb[sh_seg*HID + t*4];
    float y0 = (val.x - mean)*inv*(1.f + sc4.x) + sh4.x;
    float y1 = (val.y - mean)*inv*(1.f + sc4.y) + sh4.y;
    float y2 = (val.z - mean)*inv*(1.f + sc4.z) + sh4.z;
    float y3 = (val.w - mean)*inv*(1.f + sc4.w) + sh4.w;
    __half2 h0 = __floats2half2_rn(y0, y1);
    __half2 h1 = __floats2half2_rn(y2, y3);
    uint2 pk; pk.x = *(uint32_t*)&h0; pk.y = *(uint32_t*)&h1;
    *(uint2*)&mi_out[(size_t)r*HID + t*4] = pk;
}

// ------------------------- fp16 HMMA GEMM (ldmatrix + 3-stage) ---------------
#define AW 36
#define TILE_W (128*AW)
#define GEMM_SMEM (6*TILE_W*4)   // 108 KB

__global__ void __launch_bounds__(128)
gemm_hf(const __half* __restrict__ A, const __half* __restrict__ Bt,
        const float* __restrict__ bias, void* __restrict__ Cout,
        int M, int N, int K, int act, int outH,
        const float* __restrict__ resid, int gate_seg) {
    extern __shared__ uint32_t smw[];
    uint32_t smw_b = (uint32_t)__cvta_generic_to_shared(smw);

    int tid = threadIdx.x, lane = tid & 31, wid = tid >> 5;
    int wm = wid >> 1, wn = wid & 1;
    int row0 = blockIdx.y * 128, col0 = blockIdx.x * 128;
    int lr = lane >> 2, lc = lane & 3;
    int g = lane >> 3, lrow = lane & 7;
    int a_row = wm*64 + (g & 1)*8 + lrow;
    int a_wc  = (g >> 1)*4;
    int b_row = wn*64 + (g >> 1)*8 + lrow;
    int b_wc  = (g & 1)*4;

    float4 acc[4][8];
    #pragma unroll
    for (int i = 0; i < 4; i++)
        #pragma unroll
        for (int j = 0; j < 8; j++) acc[i][j] = make_float4(0.f,0.f,0.f,0.f);

    int KT = K >> 6;

    auto load_stage = [&](int kt, int buf) {
        const __half* gA = A  + (size_t)row0*K + kt*64;
        const __half* gB = Bt + (size_t)col0*K + kt*64;
        uint32_t* as = smw + buf*2*TILE_W;
        uint32_t* bs = as + TILE_W;
        #pragma unroll
        for (int i = 0; i < 8; i++) {
            int chunk = tid + i*128;
            int r = chunk >> 3, c = chunk & 7;
            cp16(&as[r*AW + c*4], gA + (size_t)r*K + c*8);
            cp16(&bs[r*AW + c*4], gB + (size_t)r*K + c*8);
        }
        asm volatile("cp.async.commit_group;");
    };

    load_stage(0, 0);
    if (KT > 1) load_stage(1, 1);

    for (int kt = 0; kt < KT; kt++) {
        if (kt < KT - 1) asm volatile("cp.async.wait_group 1;");
        else             asm volatile("cp.async.wait_group 0;");
        __syncthreads();
        if (kt + 2 < KT) load_stage(kt + 2, (kt + 2) % 3);

        int buf = kt % 3;
        uint32_t as_b = smw_b + buf*2*TILE_W*4;
        uint32_t bs_b = as_b + TILE_W*4;
        #pragma unroll
        for (int k16 = 0; k16 < 4; k16++) {
            uint32_t af[4][4];
            #pragma unroll
            for (int mi = 0; mi < 4; mi++)
                ldsm4(af[mi][0], af[mi][1], af[mi][2], af[mi][3],
                      as_b + (uint32_t)(((a_row + mi*16)*AW) + k16*8 + a_wc)*4);
            uint32_t bf[8][2];
            #pragma unroll
            for (int njp = 0; njp < 4; njp++)
                ldsm4(bf[2*njp][0], bf[2*njp][1], bf[2*njp+1][0], bf[2*njp+1][1],
                      bs_b + (uint32_t)(((b_row + njp*16)*AW) + k16*8 + b_wc)*4);
            #pragma unroll
            for (int mi = 0; mi < 4; mi++)
                #pragma unroll
                for (int nj = 0; nj < 8; nj++)
                    mma_f16(acc[mi][nj], af[mi], bf[nj]);
        }
        __syncthreads();
    }

    #pragma unroll
    for (int mi = 0; mi < 4; mi++) {
        #pragma unroll
        for (int nj = 0; nj < 8; nj++) {
            int r = row0 + wm*64 + mi*16 + lr;
            int c = col0 + wn*64 + nj*8 + 2*lc;
            float v[4] = {acc[mi][nj].x, acc[mi][nj].y, acc[mi][nj].z, acc[mi][nj].w};
            float b0 = bias[c], b1 = bias[c+1];
            v[0] += b0; v[1] += b1; v[2] += b0; v[3] += b1;
            if (act == 1) {
                #pragma unroll
                for (int q = 0; q < 4; q++) v[q] = fast_gelu(v[q]);
            }
            if (outH) {
                __half* Cb = (__half*)Cout;
                __half2 p0 = __floats2half2_rn(v[0], v[1]);
                __half2 p1 = __floats2half2_rn(v[2], v[3]);
                *(__half2*)&Cb[(size_t)r*N + c]     = p0;
                *(__half2*)&Cb[(size_t)(r+8)*N + c] = p1;
            } else {
                float* Cf = (float*)Cout;
                if (resid) {
                    int b = r / SEQ;
                    float g0 = g_mod[b*MOD6 + gate_seg*HID + c];
                    float g1 = g_mod[b*MOD6 + gate_seg*HID + c + 1];
                    v[0] = resid[(size_t)r*N + c]     + g0*v[0];
                    v[1] = resid[(size_t)r*N + c + 1] + g1*v[1];
                    v[2] = resid[(size_t)(r+8)*N + c]     + g0*v[2];
                    v[3] = resid[(size_t)(r+8)*N + c + 1] + g1*v[3];
                }
                *(float2*)&Cf[(size_t)r*N + c]     = make_float2(v[0], v[1]);
                *(float2*)&Cf[(size_t)(r+8)*N + c] = make_float2(v[2], v[3]);
            }
        }
    }
}

// ------------------------- qk-norm (q,k only) -> [B,NH,N,HD] fp16 -----------
__global__ void qknorm_kernel(const float* __restrict__ qn_w, const float* __restrict__ qn_b,
                              const float* __restrict__ kn_w, const float* __restrict__ kn_b) {
    int id = blockIdx.x * 8 + (threadIdx.x >> 5);
    if (id >= MROWS*32) return;
    int lane = threadIdx.x & 31;
    int r = id >> 5;
    int rem = id & 31;
    int w = rem >> 4;      // 0=q, 1=k
    int h = rem & 15;

    const __half* src = &g_qkvh[(size_t)r*3456 + w*1152 + h*72];
    float v0 = __half2float(src[lane]);
    float v1 = __half2float(src[lane + 32]);
    float v2 = (lane < 8) ? __half2float(src[lane + 64]) : 0.f;

    int b = r / SEQ, n = r % SEQ;
    __half* dst = (w == 0 ? g_qh : g_kh)
                 + (((size_t)(b*NHEAD + h)*SEQ + n)*HDIM);

    float s = v0 + v1 + v2;
    float ss = v0*v0 + v1*v1 + v2*v2;
    #pragma unroll
    for (int o = 16; o; o >>= 1) {
        s  += __shfl_xor_sync(0xffffffffu, s, o);
        ss += __shfl_xor_sync(0xffffffffu, ss, o);
    }
    float mean = s * (1.f/72.f);
    float var  = ss * (1.f/72.f) - mean*mean;
    float inv  = rsqrtf(var + 1e-5f);
    const float* ww = (w == 0) ? qn_w : kn_w;
    const float* wb = (w == 0) ? qn_b : kn_b;
    dst[lane]      = __float2half((v0 - mean)*inv*ww[lane]      + wb[lane]);
    dst[lane + 32] = __float2half((v1 - mean)*inv*ww[lane + 32] + wb[lane + 32]);
    if (lane < 8)
        dst[lane + 64] = __float2half((v2 - mean)*inv*ww[lane + 64] + wb[lane + 64]);
}

// ------------------------- V transpose: qkv v-slice -> [b][h][d][SEQ] -------
__global__ void __launch_bounds__(128) vtrans_kernel() {
    __shared__ uint32_t tile[64*37];   // stride 37 words = 74 halves
    int kt = blockIdx.x, h = blockIdx.y, b = blockIdx.z;
    int t = threadIdx.x;
    const uint32_t* src32 = (const uint32_t*)g_qkvh;

    for (int i = t; i < 64*36; i += 128) {
        int key = i / 36, w = i % 36;
        size_t off = ((size_t)(b*SEQ + kt*64 + key)*3456 + 2304 + h*72) / 2 + w;
        tile[key*37 + w] = src32[off];
    }
    __syncthreads();
    const __half* tileh = (const __half*)tile;
    uint32_t* dst32 = (uint32_t*)g_vth;
    for (int i = t; i < 72*32; i += 128) {
        int d = i / 32, w2 = i % 32;
        __half2 p;
        p.x = tileh[(2*w2)*74 + d];
        p.y = tileh[(2*w2 + 1)*74 + d];
        dst32[((size_t)((b*NHEAD + h)*HDIM + d)*SEQ)/2 + kt*32 + w2] = *(uint32_t*)&p;
    }
}

// ------------------------- fp16 tensor-core flash attention -----------------
#define AT_QW (128*36)
#define AT_KW (64*36)
#define AT_VW (72*36)
#define ATTN_SMEM ((AT_QW + 2*AT_KW + 2*AT_VW)*4)   // 57.6 KB

__global__ void __launch_bounds__(256) attn_h() {
    extern __shared__ uint32_t smw[];
    uint32_t* Qs = smw;
    uint32_t* Kb = Qs + AT_QW;
    uint32_t* Vb = Kb + 2*AT_KW;

    int b = blockIdx.z, h = blockIdx.y, q0 = blockIdx.x*128;
    int tid = threadIdx.x, lane = tid & 31, wid = tid >> 5;
    int lr = lane >> 2, lc = lane & 3;
    int wr = wid * 16;
    size_t base = (size_t)(b*NHEAD + h) * SEQ * HDIM;
    const __half* vbase = &g_vth[(size_t)(b*NHEAD + h) * HDIM * SEQ];
    const float scale = 0.11785113019775793f;

    auto load_stage = [&](int t, int buf) {
        const __half* kg = &g_kh[base + (size_t)(t*64)*HDIM];
        for (int i = tid; i < 576; i += 256) {
            int r = i / 9, c = i % 9;
            cp16(&Kb[buf*AT_KW + r*36 + c*4], kg + r*HDIM + c*8);
        }
        const __half* vg = vbase + t*64;
        for (int i = tid; i < 576; i += 256) {
            int d = i >> 3, c = i & 7;
            cp16(&Vb[buf*AT_VW + d*36 + c*4], vg + (size_t)d*SEQ + c*8);
        }
        asm volatile("cp.async.commit_group;");
    };

    {
        const uint4* qg = (const uint4*)&g_qh[base + (size_t)q0*HDIM];
        for (int i = tid; i < 128*9; i += 256) {
            int r = i / 9, c = i % 9;
            *(uint4*)&Qs[r*36 + c*4] = qg[i];
        }
    }
    load_stage(0, 0);

    float4 o[9];
    #pragma unroll
    for (int i = 0; i < 9; i++) o[i] = make_float4(0.f,0.f,0.f,0.f);
    float m_lo = -INFINITY, m_hi = -INFINITY, l_lo = 0.f, l_hi = 0.f;

    for (int t = 0; t < 16; t++) {
        asm volatile("cp.async.wait_group 0;");
        __syncthreads();
        if (t + 1 < 16) load_stage(t + 1, (t + 1) & 1);
        int buf = t & 1;
        const uint32_t* Ks = &Kb[buf*AT_KW];
        const uint32_t* Vt = &Vb[buf*AT_VW];

        float4 sc[8];
        #pragma unroll
        for (int i = 0; i < 8; i++) sc[i] = make_float4(0.f,0.f,0.f,0.f);
        #pragma unroll
        for (int k16 = 0; k16 < 4; k16++) {
            int kw = k16*8 + lc;
            uint32_t af[4];
            af[0] = Qs[(wr+lr)*36 + kw];
            af[1] = Qs[(wr+8+lr)*36 + kw];
            af[2] = Qs[(wr+lr)*36 + kw + 4];
            af[3] = Qs[(wr+8+lr)*36 + kw + 4];
            #pragma unroll
            for (int nj = 0; nj < 8; nj++) {
                int cc = nj*8 + lr;
                uint32_t bf[2] = {Ks[cc*36 + kw], Ks[cc*36 + kw + 4]};
                mma_f16(sc[nj], af, bf);
            }
        }
        {
            int kw = 32 + lc;
            uint32_t a0 = Qs[(wr+lr)*36 + kw];
            uint32_t a1 = Qs[(wr+8+lr)*36 + kw];
            #pragma unroll
            for (int nj = 0; nj < 8; nj++) {
                int cc = nj*8 + lr;
                mma_f16_k8(sc[nj], a0, a1, Ks[cc*36 + kw]);
            }
        }

        float tmax_lo = -INFINITY, tmax_hi = -INFINITY;
        #pragma unroll
        for (int nj = 0; nj < 8; nj++) {
            sc[nj].x *= scale; sc[nj].y *= scale; sc[nj].z *= scale; sc[nj].w *= scale;
            tmax_lo = fmaxf(tmax_lo, fmaxf(sc[nj].x, sc[nj].y));
            tmax_hi = fmaxf(tmax_hi, fmaxf(sc[nj].z, sc[nj].w));
        }
        tmax_lo = fmaxf(tmax_lo, __shfl_xor_sync(0xffffffffu, tmax_lo, 1));
        tmax_lo = fmaxf(tmax_lo, __shfl_xor_sync(0xffffffffu, tmax_lo, 2));
        tmax_hi = fmaxf(tmax_hi, __shfl_xor_sync(0xffffffffu, tmax_hi, 1));
        tmax_hi = fmaxf(tmax_hi, __shfl_xor_sync(0xffffffffu, tmax_hi, 2));

        float mn_lo = fmaxf(m_lo, tmax_lo);
        float mn_hi = fmaxf(m_hi, tmax_hi);
        float corr_lo = __expf(m_lo - mn_lo);
        float corr_hi = __expf(m_hi - mn_hi);
        l_lo *= corr_lo; l_hi *= corr_hi;
        #pragma unroll
        for (int i = 0; i < 9; i++) {
            o[i].x *= corr_lo; o[i].y *= corr_lo;
            o[i].z *= corr_hi; o[i].w *= corr_hi;
        }
        uint32_t ph[8][2];
        float sum_lo = 0.f, sum_hi = 0.f;
        #pragma unroll
        for (int nj = 0; nj < 8; nj++) {
            float px = __expf(sc[nj].x - mn_lo);
            float py = __expf(sc[nj].y - mn_lo);
            float pz = __expf(sc[nj].z - mn_hi);
            float pw = __expf(sc[nj].w - mn_hi);
            sum_lo += px + py; sum_hi += pz + pw;
            __half2 plo = __floats2half2_rn(px, py);
            __half2 phi = __floats2half2_rn(pz, pw);
            ph[nj][0] = *(uint32_t*)&plo;
            ph[nj][1] = *(uint32_t*)&phi;
        }
        sum_lo += __shfl_xor_sync(0xffffffffu, sum_lo, 1);
        sum_lo += __shfl_xor_sync(0xffffffffu, sum_lo, 2);
        sum_hi += __shfl_xor_sync(0xffffffffu, sum_hi, 1);
        sum_hi += __shfl_xor_sync(0xffffffffu, sum_hi, 2);
        l_lo += sum_lo; l_hi += sum_hi;
        m_lo = mn_lo; m_hi = mn_hi;

        #pragma unroll
        for (int k16 = 0; k16 < 4; k16++) {
            int kw = k16*8 + lc;
            uint32_t af[4];
            af[0] = ph[2*k16][0];
            af[1] = ph[2*k16][1];
            af[2] = ph[2*k16+1][0];
            af[3] = ph[2*k16+1][1];
            #pragma unroll
            for (int n9 = 0; n9 < 9; n9++) {
                int cc = n9*8 + lr;
                uint32_t bf[2] = {Vt[cc*36 + kw], Vt[cc*36 + kw + 4]};
                mma_f16(o[n9], af, bf);
            }
        }
    }

    float inv_lo = 1.f / l_lo, inv_hi = 1.f / l_hi;
    int r = b*SEQ + q0 + wr + lr;
    #pragma unroll
    for (int n9 = 0; n9 < 9; n9++) {
        int c = h*HDIM + n9*8 + 2*lc;
        __half2 p0 = __floats2half2_rn(o[n9].x*inv_lo, o[n9].y*inv_lo);
        __half2 p1 = __floats2half2_rn(o[n9].z*inv_hi, o[n9].w*inv_hi);
        *(__half2*)&g_oh[(size_t)r*HID + c]     = p0;
        *(__half2*)&g_oh[(size_t)(r+8)*HID + c] = p1;
    }
}

// ---------------------------------------------------------------------------
extern "C" void kernel_launch(void* const* d_in, const int* in_sizes, int n_in,
                              void* d_out, int out_size) {
    const float* x      = (const float*)d_in[0];
    const float* c      = (const float*)d_in[1];
    const float* w_ada  = (const float*)d_in[2];
    const float* b_ada  = (const float*)d_in[3];
    const float* w_qkv  = (const float*)d_in[4];
    const float* b_qkv  = (const float*)d_in[5];
    const float* qn_w   = (const float*)d_in[6];
    const float* qn_b   = (const float*)d_in[7];
    const float* kn_w   = (const float*)d_in[8];
    const float* kn_b   = (const float*)d_in[9];
    const float* w_proj = (const float*)d_in[10];
    const float* b_proj = (const float*)d_in[11];
    const float* w_fc1  = (const float*)d_in[12];
    const float* b_fc1  = (const float*)d_in[13];
    const float* w_fc2  = (const float*)d_in[14];
    const float* b_fc2  = (const float*)d_in[15];
    float* out = (float*)d_out;

    float *p_x1;
    __half *p_aih, *p_qkvh, *p_oh, *p_mih, *p_hh;
    __half *p_wqkt, *p_wpt, *p_wf1t, *p_wf2t;
    cudaGetSymbolAddress((void**)&p_x1,   g_x1);
    cudaGetSymbolAddress((void**)&p_aih,  g_aih);
    cudaGetSymbolAddress((void**)&p_qkvh, g_qkvh);
    cudaGetSymbolAddress((void**)&p_oh,   g_oh);
    cudaGetSymbolAddress((void**)&p_mih,  g_mih);
    cudaGetSymbolAddress((void**)&p_hh,   g_hh);
    cudaGetSymbolAddress((void**)&p_wqkt, g_wqkt);
    cudaGetSymbolAddress((void**)&p_wpt,  g_wpt);
    cudaGetSymbolAddress((void**)&p_wf1t, g_wf1t);
    cudaGetSymbolAddress((void**)&p_wf2t, g_wf2t);

    static cudaStream_t s1;
    static cudaEvent_t ev_fork, ev_wq, ev_wall, ev_qkv, ev_vt;
    static int attr_set = 0;
    if (!attr_set) {
        cudaFuncSetAttribute(gemm_hf, cudaFuncAttributeMaxDynamicSharedMemorySize, GEMM_SMEM);
        cudaFuncSetAttribute(attn_h, cudaFuncAttributeMaxDynamicSharedMemorySize, ATTN_SMEM);
        cudaStreamCreateWithFlags(&s1, cudaStreamNonBlocking);
        cudaEventCreateWithFlags(&ev_fork, cudaEventDisableTiming);
        cudaEventCreateWithFlags(&ev_wq,   cudaEventDisableTiming);
        cudaEventCreateWithFlags(&ev_wall, cudaEventDisableTiming);
        cudaEventCreateWithFlags(&ev_qkv,  cudaEventDisableTiming);
        cudaEventCreateWithFlags(&ev_vt,   cudaEventDisableTiming);
        attr_set = 1;
    }

    // ---- fork: weight transposes on side stream s1 ----
    cudaEventRecord(ev_fork, 0);
    cudaStreamWaitEvent(s1, ev_fork, 0);
    wtrans_kernel<<<dim3(3*HID/64, HID/64), 256, 0, s1>>>(w_qkv, p_wqkt, HID, 3*HID);
    cudaEventRecord(ev_wq, s1);
    wtrans_kernel<<<dim3(HID/64, HID/64), 256, 0, s1>>>(w_proj, p_wpt, HID, HID);
    wtrans_kernel<<<dim3(DFF/64, HID/64), 256, 0, s1>>>(w_fc1, p_wf1t, HID, DFF);
    wtrans_kernel<<<dim3(HID/64, DFF/64), 256, 0, s1>>>(w_fc2, p_wf2t, DFF, HID);
    cudaEventRecord(ev_wall, s1);

    // ---- main chain ----
    adaln_kernel<<<MOD6/128, 128>>>(c, w_ada, b_ada);
    modulate_kernel<<<MROWS, 288>>>(x, nullptr, 0, 1, -1, nullptr, p_aih);
    cudaStreamWaitEvent(0, ev_wq, 0);
    gemm_hf<<<dim3(3*HID/128, MROWS/128), 128, GEMM_SMEM>>>(p_aih, p_wqkt, b_qkv, p_qkvh,
                                                            MROWS, 3*HID, HID, 0, 1, nullptr, 0);
    cudaEventRecord(ev_qkv, 0);
    // vtrans on s1 (after its wtrans work), concurrent with qknorm on main
    cudaStreamWaitEvent(s1, ev_qkv, 0);
    vtrans_kernel<<<dim3(SEQ/64, NHEAD, BB), 128, 0, s1>>>();
    cudaEventRecord(ev_vt, s1);
    qknorm_kernel<<<MROWS*32/8, 256>>>(qn_w, qn_b, kn_w, kn_b);
    cudaStreamWaitEvent(0, ev_vt, 0);
    attn_h<<<dim3(SEQ/128, NHEAD, BB), 256, ATTN_SMEM>>>();
    cudaStreamWaitEvent(0, ev_wall, 0);
    // proj with fused residual: x1 = x + g_msa * (o @ w_proj + b)
    gemm_hf<<<dim3(HID/128, MROWS/128), 128, GEMM_SMEM>>>(p_oh, p_wpt, b_proj, p_x1,
                                                          MROWS, HID, HID, 0, 0, x, 2);
    modulate_kernel<<<MROWS, 288>>>(p_x1, nullptr, 3, 4, -1, nullptr, p_mih);
    gemm_hf<<<dim3(DFF/128, MROWS/128), 128, GEMM_SMEM>>>(p_mih, p_wf1t, b_fc1, p_hh,
                                                          MROWS, DFF, HID, 1, 1, nullptr, 0);
    gemm_hf<<<dim3(HID/128, MROWS/128), 128, GEMM_SMEM>>>(p_hh, p_wf2t, b_fc2, out,
                                                          MROWS, HID, DFF, 0, 0, p_x1, 5);
}

// round 12
// speedup vs baseline: 1.0005x; 1.0005x over previous
#include <cuda_runtime.h>
#include <cuda_fp16.h>
#include <math.h>
#include <stdint.h>

#define BB 8
#define SEQ 1024
#define HID 1152
#define NHEAD 16
#define HDIM 72
#define DFF 4608
#define MROWS (BB*SEQ)      // 8192
#define MOD6 (6*HID)        // 6912

// ------------------------- scratch (__device__ globals, no allocs) ----------
__device__ float g_mod[BB*MOD6];
__device__ float g_x1[MROWS*HID];
// fp16 activations
__device__ __half g_aih[(size_t)MROWS*HID];
__device__ __half g_qkvh[(size_t)MROWS*3*HID];
__device__ __half g_qh[MROWS*HID];
__device__ __half g_kh[MROWS*HID];
__device__ __half g_vth[MROWS*HID];          // V transposed per head: [b][h][d][SEQ]
__device__ __half g_oh[MROWS*HID];
__device__ __half g_mih[(size_t)MROWS*HID];
__device__ __half g_hh[(size_t)MROWS*DFF];
// transposed fp16 weights  Wt[N][K]
__device__ __half g_wqkt[(size_t)3*HID*HID];
__device__ __half g_wpt[(size_t)HID*HID];
__device__ __half g_wf1t[(size_t)DFF*HID];
__device__ __half g_wf2t[(size_t)HID*DFF];

// ------------------------- helpers ------------------------------------------
__device__ __forceinline__ void cp16(void* smem_dst, const void* gsrc) {
    unsigned s = (unsigned)__cvta_generic_to_shared(smem_dst);
    asm volatile("cp.async.cg.shared.global [%0], [%1], 16;" :: "r"(s), "l"(gsrc));
}
__device__ __forceinline__ void mma_f16(float4& d, const uint32_t* a, const uint32_t* b) {
    asm volatile(
        "mma.sync.aligned.m16n8k16.row.col.f32.f16.f16.f32 "
        "{%0,%1,%2,%3}, {%4,%5,%6,%7}, {%8,%9}, {%0,%1,%2,%3};"
        : "+f"(d.x), "+f"(d.y), "+f"(d.z), "+f"(d.w)
        : "r"(a[0]), "r"(a[1]), "r"(a[2]), "r"(a[3]), "r"(b[0]), "r"(b[1]));
}
__device__ __forceinline__ void mma_f16_k8(float4& d, uint32_t a0, uint32_t a1, uint32_t b0) {
    asm volatile(
        "mma.sync.aligned.m16n8k8.row.col.f32.f16.f16.f32 "
        "{%0,%1,%2,%3}, {%4,%5}, {%6}, {%0,%1,%2,%3};"
        : "+f"(d.x), "+f"(d.y), "+f"(d.z), "+f"(d.w)
        : "r"(a0), "r"(a1), "r"(b0));
}
__device__ __forceinline__ void ldsm4(uint32_t& r0, uint32_t& r1, uint32_t& r2, uint32_t& r3,
                                      uint32_t addr) {
    asm volatile("ldmatrix.sync.aligned.m8n8.x4.shared.b16 {%0,%1,%2,%3}, [%4];"
                 : "=r"(r0), "=r"(r1), "=r"(r2), "=r"(r3) : "r"(addr));
}
__device__ __forceinline__ float fast_gelu(float u) {
    float e = __expf(-1.5957691216057308f * fmaf(0.044715f*u*u, u, u));
    return __fdividef(u, 1.f + e);
}

// ------------------------- weight transpose fp32[K][N] -> fp16[N][K] --------
__global__ void __launch_bounds__(256)
wtrans_kernel(const float* __restrict__ in, __half* __restrict__ out, int K, int N) {
    __shared__ float tile[64][65];
    int k0 = blockIdx.y*64, n0 = blockIdx.x*64;
    int t = threadIdx.x;
    #pragma unroll
    for (int i = 0; i < 4; i++) {
        int idx = t + i*256;
        int r = idx >> 4, c = idx & 15;
        float4 v = *(const float4*)&in[(size_t)(k0 + r)*N + n0 + c*4];
        tile[r][c*4+0] = v.x; tile[r][c*4+1] = v.y;
        tile[r][c*4+2] = v.z; tile[r][c*4+3] = v.w;
    }
    __syncthreads();
    #pragma unroll
    for (int i = 0; i < 8; i++) {
        int idx = t + i*256;
        int n = idx >> 5, c = idx & 31;
        __half2 h = __floats2half2_rn(tile[2*c][n], tile[2*c+1][n]);
        *(__half2*)&out[(size_t)(n0 + n)*K + k0 + 2*c] = h;
    }
}

// ------------------------- fused silu + adaLN (w_ada read ONCE) -------------
__global__ void __launch_bounds__(128)
adaln_kernel(const float* __restrict__ c, const float* __restrict__ w_ada,
             const float* __restrict__ b_ada) {
    __shared__ float sc[BB*HID];   // 36 KB: silu(c) for all 8 batches
    int tid = threadIdx.x;
    for (int i = tid; i < BB*HID; i += 128) {
        float s = c[i];
        sc[i] = s / (1.f + expf(-s));
    }
    __syncthreads();
    int j = blockIdx.x*128 + tid;
    float bj = b_ada[j];
    float acc[BB];
    #pragma unroll
    for (int b = 0; b < BB; b++) acc[b] = bj;
    for (int k = 0; k < HID; k++) {
        float w = w_ada[(size_t)k*MOD6 + j];
        #pragma unroll
        for (int b = 0; b < BB; b++) acc[b] = fmaf(sc[b*HID + k], w, acc[b]);
    }
    #pragma unroll
    for (int b = 0; b < BB; b++) g_mod[b*MOD6 + j] = acc[b];
}

// --------------- fused (optional residual+gate) + LN + modulate -> fp16 -----
__global__ void __launch_bounds__(288)
modulate_kernel(const float* __restrict__ x, const float* __restrict__ res,
                int sh_seg, int sc_seg, int g_seg,
                float* __restrict__ x1_out, __half* __restrict__ mi_out) {
    int r = blockIdx.x, b = r / SEQ, t = threadIdx.x;
    const float* modb = &g_mod[b*MOD6];

    float4 val = *(const float4*)&x[(size_t)r*HID + t*4];
    if (res) {
        float4 rv = *(const float4*)&res[(size_t)r*HID + t*4];
        float4 gv = *(const float4*)&modb[g_seg*HID + t*4];
        val.x = fmaf(gv.x, rv.x, val.x); val.y = fmaf(gv.y, rv.y, val.y);
        val.z = fmaf(gv.z, rv.z, val.z); val.w = fmaf(gv.w, rv.w, val.w);
    }
    if (x1_out) *(float4*)&x1_out[(size_t)r*HID + t*4] = val;

    float s  = val.x + val.y + val.z + val.w;
    float ss = val.x*val.x + val.y*val.y + val.z*val.z + val.w*val.w;
    int lane = t & 31, wid = t >> 5;
    #pragma unroll
    for (int o = 16; o; o >>= 1) {
        s  += __shfl_xor_sync(0xffffffffu, s, o);
        ss += __shfl_xor_sync(0xffffffffu, ss, o);
    }
    __shared__ float sh1[9], sh2[9];
    if (lane == 0) { sh1[wid] = s; sh2[wid] = ss; }
    __syncthreads();
    if (t == 0) {
        float a = 0.f, bb = 0.f;
        #pragma unroll
        for (int i = 0; i < 9; i++) { a += sh1[i]; bb += sh2[i]; }
        sh1[0] = a; sh2[0] = bb;
    }
    __syncthreads();
    float mean = sh1[0] * (1.f/HID);
    float var  = sh2[0] * (1.f/HID) - mean*mean;
    float inv  = rsqrtf(var + 1e-6f);

    float4 sc4 = *(const float4*)&modb[sc_seg*HID + t*4];
    float4 sh4 = *(const float4*)&modb[sh_seg*HID + t*4];
    float y0 = (val.x - mean)*inv*(1.f + sc4.x) + sh4.x;
    float y1 = (val.y - mean)*inv*(1.f + sc4.y) + sh4.y;
    float y2 = (val.z - mean)*inv*(1.f + sc4.z) + sh4.z;
    float y3 = (val.w - mean)*inv*(1.f + sc4.w) + sh4.w;
    __half2 h0 = __floats2half2_rn(y0, y1);
    __half2 h1 = __floats2half2_rn(y2, y3);
    uint2 pk; pk.x = *(uint32_t*)&h0; pk.y = *(uint32_t*)&h1;
    *(uint2*)&mi_out[(size_t)r*HID + t*4] = pk;
}

// ------------------------- fp16 HMMA GEMM (ldmatrix + 3-stage) ---------------
#define AW 36
#define TILE_W (128*AW)
#define GEMM_SMEM (6*TILE_W*4)   // 108 KB

__global__ void __launch_bounds__(128)
gemm_hf(const __half* __restrict__ A, const __half* __restrict__ Bt,
        const float* __restrict__ bias, void* __restrict__ Cout,
        int M, int N, int K, int act, int outH,
        const float* __restrict__ resid, int gate_seg) {
    extern __shared__ uint32_t smw[];
    uint32_t smw_b = (uint32_t)__cvta_generic_to_shared(smw);

    int tid = threadIdx.x, lane = tid & 31, wid = tid >> 5;
    int wm = wid >> 1, wn = wid & 1;
    int row0 = blockIdx.y * 128, col0 = blockIdx.x * 128;
    int lr = lane >> 2, lc = lane & 3;
    int g = lane >> 3, lrow = lane & 7;
    int a_row = wm*64 + (g & 1)*8 + lrow;
    int a_wc  = (g >> 1)*4;
    int b_row = wn*64 + (g >> 1)*8 + lrow;
    int b_wc  = (g & 1)*4;

    float4 acc[4][8];
    #pragma unroll
    for (int i = 0; i < 4; i++)
        #pragma unroll
        for (int j = 0; j < 8; j++) acc[i][j] = make_float4(0.f,0.f,0.f,0.f);

    int KT = K >> 6;

    auto load_stage = [&](int kt, int buf) {
        const __half* gA = A  + (size_t)row0*K + kt*64;
        const __half* gB = Bt + (size_t)col0*K + kt*64;
        uint32_t* as = smw + buf*2*TILE_W;
        uint32_t* bs = as + TILE_W;
        #pragma unroll
        for (int i = 0; i < 8; i++) {
            int chunk = tid + i*128;
            int r = chunk >> 3, c = chunk & 7;
            cp16(&as[r*AW + c*4], gA + (size_t)r*K + c*8);
            cp16(&bs[r*AW + c*4], gB + (size_t)r*K + c*8);
        }
        asm volatile("cp.async.commit_group;");
    };

    load_stage(0, 0);
    if (KT > 1) load_stage(1, 1);

    for (int kt = 0; kt < KT; kt++) {
        if (kt < KT - 1) asm volatile("cp.async.wait_group 1;");
        else             asm volatile("cp.async.wait_group 0;");
        __syncthreads();
        if (kt + 2 < KT) load_stage(kt + 2, (kt + 2) % 3);

        int buf = kt % 3;
        uint32_t as_b = smw_b + buf*2*TILE_W*4;
        uint32_t bs_b = as_b + TILE_W*4;
        #pragma unroll
        for (int k16 = 0; k16 < 4; k16++) {
            uint32_t af[4][4];
            #pragma unroll
            for (int mi = 0; mi < 4; mi++)
                ldsm4(af[mi][0], af[mi][1], af[mi][2], af[mi][3],
                      as_b + (uint32_t)(((a_row + mi*16)*AW) + k16*8 + a_wc)*4);
            uint32_t bf[8][2];
            #pragma unroll
            for (int njp = 0; njp < 4; njp++)
                ldsm4(bf[2*njp][0], bf[2*njp][1], bf[2*njp+1][0], bf[2*njp+1][1],
                      bs_b + (uint32_t)(((b_row + njp*16)*AW) + k16*8 + b_wc)*4);
            #pragma unroll
            for (int mi = 0; mi < 4; mi++)
                #pragma unroll
                for (int nj = 0; nj < 8; nj++)
                    mma_f16(acc[mi][nj], af[mi], bf[nj]);
        }
        __syncthreads();
    }

    #pragma unroll
    for (int mi = 0; mi < 4; mi++) {
        #pragma unroll
        for (int nj = 0; nj < 8; nj++) {
            int r = row0 + wm*64 + mi*16 + lr;
            int c = col0 + wn*64 + nj*8 + 2*lc;
            float v[4] = {acc[mi][nj].x, acc[mi][nj].y, acc[mi][nj].z, acc[mi][nj].w};
            float b0 = bias[c], b1 = bias[c+1];
            v[0] += b0; v[1] += b1; v[2] += b0; v[3] += b1;
            if (act == 1) {
                #pragma unroll
                for (int q = 0; q < 4; q++) v[q] = fast_gelu(v[q]);
            }
            if (outH) {
                __half* Cb = (__half*)Cout;
                __half2 p0 = __floats2half2_rn(v[0], v[1]);
                __half2 p1 = __floats2half2_rn(v[2], v[3]);
                *(__half2*)&Cb[(size_t)r*N + c]     = p0;
                *(__half2*)&Cb[(size_t)(r+8)*N + c] = p1;
            } else {
                float* Cf = (float*)Cout;
                if (resid) {
                    int b = r / SEQ;
                    float g0 = g_mod[b*MOD6 + gate_seg*HID + c];
                    float g1 = g_mod[b*MOD6 + gate_seg*HID + c + 1];
                    v[0] = resid[(size_t)r*N + c]     + g0*v[0];
                    v[1] = resid[(size_t)r*N + c + 1] + g1*v[1];
                    v[2] = resid[(size_t)(r+8)*N + c]     + g0*v[2];
                    v[3] = resid[(size_t)(r+8)*N + c + 1] + g1*v[3];
                }
                *(float2*)&Cf[(size_t)r*N + c]     = make_float2(v[0], v[1]);
                *(float2*)&Cf[(size_t)(r+8)*N + c] = make_float2(v[2], v[3]);
            }
        }
    }
}

// ------------------------- qk-norm (q,k only) -> [B,NH,N,HD] fp16 -----------
__global__ void qknorm_kernel(const float* __restrict__ qn_w, const float* __restrict__ qn_b,
                              const float* __restrict__ kn_w, const float* __restrict__ kn_b) {
    int id = blockIdx.x * 8 + (threadIdx.x >> 5);
    if (id >= MROWS*32) return;
    int lane = threadIdx.x & 31;
    int r = id >> 5;
    int rem = id & 31;
    int w = rem >> 4;      // 0=q, 1=k
    int h = rem & 15;

    const __half* src = &g_qkvh[(size_t)r*3456 + w*1152 + h*72];
    float v0 = __half2float(src[lane]);
    float v1 = __half2float(src[lane + 32]);
    float v2 = (lane < 8) ? __half2float(src[lane + 64]) : 0.f;

    int b = r / SEQ, n = r % SEQ;
    __half* dst = (w == 0 ? g_qh : g_kh)
                 + (((size_t)(b*NHEAD + h)*SEQ + n)*HDIM);

    float s = v0 + v1 + v2;
    float ss = v0*v0 + v1*v1 + v2*v2;
    #pragma unroll
    for (int o = 16; o; o >>= 1) {
        s  += __shfl_xor_sync(0xffffffffu, s, o);
        ss += __shfl_xor_sync(0xffffffffu, ss, o);
    }
    float mean = s * (1.f/72.f);
    float var  = ss * (1.f/72.f) - mean*mean;
    float inv  = rsqrtf(var + 1e-5f);
    const float* ww = (w == 0) ? qn_w : kn_w;
    const float* wb = (w == 0) ? qn_b : kn_b;
    dst[lane]      = __float2half((v0 - mean)*inv*ww[lane]      + wb[lane]);
    dst[lane + 32] = __float2half((v1 - mean)*inv*ww[lane + 32] + wb[lane + 32]);
    if (lane < 8)
        dst[lane + 64] = __float2half((v2 - mean)*inv*ww[lane + 64] + wb[lane + 64]);
}

// ------------------------- V transpose: qkv v-slice -> [b][h][d][SEQ] -------
__global__ void __launch_bounds__(128) vtrans_kernel() {
    __shared__ uint32_t tile[64*37];   // stride 37 words = 74 halves
    int kt = blockIdx.x, h = blockIdx.y, b = blockIdx.z;
    int t = threadIdx.x;
    const uint32_t* src32 = (const uint32_t*)g_qkvh;

    for (int i = t; i < 64*36; i += 128) {
        int key = i / 36, w = i % 36;
        size_t off = ((size_t)(b*SEQ + kt*64 + key)*3456 + 2304 + h*72) / 2 + w;
        tile[key*37 + w] = src32[off];
    }
    __syncthreads();
    const __half* tileh = (const __half*)tile;
    uint32_t* dst32 = (uint32_t*)g_vth;
    for (int i = t; i < 72*32; i += 128) {
        int d = i / 32, w2 = i % 32;
        __half2 p;
        p.x = tileh[(2*w2)*74 + d];
        p.y = tileh[(2*w2 + 1)*74 + d];
        dst32[((size_t)((b*NHEAD + h)*HDIM + d)*SEQ)/2 + kt*32 + w2] = *(uint32_t*)&p;
    }
}

// ------------------------- fp16 tensor-core flash attention -----------------
#define AT_QW (128*36)
#define AT_KW (64*36)
#define AT_VW (72*36)
#define ATTN_SMEM ((AT_QW + 2*AT_KW + 2*AT_VW)*4)   // 57.6 KB

__global__ void __launch_bounds__(256) attn_h() {
    extern __shared__ uint32_t smw[];
    uint32_t* Qs = smw;
    uint32_t* Kb = Qs + AT_QW;
    uint32_t* Vb = Kb + 2*AT_KW;

    int b = blockIdx.z, h = blockIdx.y, q0 = blockIdx.x*128;
    int tid = threadIdx.x, lane = tid & 31, wid = tid >> 5;
    int lr = lane >> 2, lc = lane & 3;
    int wr = wid * 16;
    size_t base = (size_t)(b*NHEAD + h) * SEQ * HDIM;
    const __half* vbase = &g_vth[(size_t)(b*NHEAD + h) * HDIM * SEQ];
    const float scale = 0.11785113019775793f;

    auto load_stage = [&](int t, int buf) {
        const __half* kg = &g_kh[base + (size_t)(t*64)*HDIM];
        for (int i = tid; i < 576; i += 256) {
            int r = i / 9, c = i % 9;
            cp16(&Kb[buf*AT_KW + r*36 + c*4], kg + r*HDIM + c*8);
        }
        const __half* vg = vbase + t*64;
        for (int i = tid; i < 576; i += 256) {
            int d = i >> 3, c = i & 7;
            cp16(&Vb[buf*AT_VW + d*36 + c*4], vg + (size_t)d*SEQ + c*8);
        }
        asm volatile("cp.async.commit_group;");
    };

    {
        const uint4* qg = (const uint4*)&g_qh[base + (size_t)q0*HDIM];
        for (int i = tid; i < 128*9; i += 256) {
            int r = i / 9, c = i % 9;
            *(uint4*)&Qs[r*36 + c*4] = qg[i];
        }
    }
    load_stage(0, 0);

    float4 o[9];
    #pragma unroll
    for (int i = 0; i < 9; i++) o[i] = make_float4(0.f,0.f,0.f,0.f);
    float m_lo = -INFINITY, m_hi = -INFINITY, l_lo = 0.f, l_hi = 0.f;

    for (int t = 0; t < 16; t++) {
        asm volatile("cp.async.wait_group 0;");
        __syncthreads();
        if (t + 1 < 16) load_stage(t + 1, (t + 1) & 1);
        int buf = t & 1;
        const uint32_t* Ks = &Kb[buf*AT_KW];
        const uint32_t* Vt = &Vb[buf*AT_VW];

        float4 sc[8];
        #pragma unroll
        for (int i = 0; i < 8; i++) sc[i] = make_float4(0.f,0.f,0.f,0.f);
        #pragma unroll
        for (int k16 = 0; k16 < 4; k16++) {
            int kw = k16*8 + lc;
            uint32_t af[4];
            af[0] = Qs[(wr+lr)*36 + kw];
            af[1] = Qs[(wr+8+lr)*36 + kw];
            af[2] = Qs[(wr+lr)*36 + kw + 4];
            af[3] = Qs[(wr+8+lr)*36 + kw + 4];
            #pragma unroll
            for (int nj = 0; nj < 8; nj++) {
                int cc = nj*8 + lr;
                uint32_t bf[2] = {Ks[cc*36 + kw], Ks[cc*36 + kw + 4]};
                mma_f16(sc[nj], af, bf);
            }
        }
        {
            int kw = 32 + lc;
            uint32_t a0 = Qs[(wr+lr)*36 + kw];
            uint32_t a1 = Qs[(wr+8+lr)*36 + kw];
            #pragma unroll
            for (int nj = 0; nj < 8; nj++) {
                int cc = nj*8 + lr;
                mma_f16_k8(sc[nj], a0, a1, Ks[cc*36 + kw]);
            }
        }

        float tmax_lo = -INFINITY, tmax_hi = -INFINITY;
        #pragma unroll
        for (int nj = 0; nj < 8; nj++) {
            sc[nj].x *= scale; sc[nj].y *= scale; sc[nj].z *= scale; sc[nj].w *= scale;
            tmax_lo = fmaxf(tmax_lo, fmaxf(sc[nj].x, sc[nj].y));
            tmax_hi = fmaxf(tmax_hi, fmaxf(sc[nj].z, sc[nj].w));
        }
        tmax_lo = fmaxf(tmax_lo, __shfl_xor_sync(0xffffffffu, tmax_lo, 1));
        tmax_lo = fmaxf(tmax_lo, __shfl_xor_sync(0xffffffffu, tmax_lo, 2));
        tmax_hi = fmaxf(tmax_hi, __shfl_xor_sync(0xffffffffu, tmax_hi, 1));
        tmax_hi = fmaxf(tmax_hi, __shfl_xor_sync(0xffffffffu, tmax_hi, 2));

        float mn_lo = fmaxf(m_lo, tmax_lo);
        float mn_hi = fmaxf(m_hi, tmax_hi);
        float corr_lo = __expf(m_lo - mn_lo);
        float corr_hi = __expf(m_hi - mn_hi);
        l_lo *= corr_lo; l_hi *= corr_hi;
        #pragma unroll
        for (int i = 0; i < 9; i++) {
            o[i].x *= corr_lo; o[i].y *= corr_lo;
            o[i].z *= corr_hi; o[i].w *= corr_hi;
        }
        uint32_t ph[8][2];
        float sum_lo = 0.f, sum_hi = 0.f;
        #pragma unroll
        for (int nj = 0; nj < 8; nj++) {
            float px = __expf(sc[nj].x - mn_lo);
            float py = __expf(sc[nj].y - mn_lo);
            float pz = __expf(sc[nj].z - mn_hi);
            float pw = __expf(sc[nj].w - mn_hi);
            sum_lo += px + py; sum_hi += pz + pw;
            __half2 plo = __floats2half2_rn(px, py);
            __half2 phi = __floats2half2_rn(pz, pw);
            ph[nj][0] = *(uint32_t*)&plo;
            ph[nj][1] = *(uint32_t*)&phi;
        }
        sum_lo += __shfl_xor_sync(0xffffffffu, sum_lo, 1);
        sum_lo += __shfl_xor_sync(0xffffffffu, sum_lo, 2);
        sum_hi += __shfl_xor_sync(0xffffffffu, sum_hi, 1);
        sum_hi += __shfl_xor_sync(0xffffffffu, sum_hi, 2);
        l_lo += sum_lo; l_hi += sum_hi;
        m_lo = mn_lo; m_hi = mn_hi;

        #pragma unroll
        for (int k16 = 0; k16 < 4; k16++) {
            int kw = k16*8 + lc;
            uint32_t af[4];
            af[0] = ph[2*k16][0];
            af[1] = ph[2*k16][1];
            af[2] = ph[2*k16+1][0];
            af[3] = ph[2*k16+1][1];
            #pragma unroll
            for (int n9 = 0; n9 < 9; n9++) {
                int cc = n9*8 + lr;
                uint32_t bf[2] = {Vt[cc*36 + kw], Vt[cc*36 + kw + 4]};
                mma_f16(o[n9], af, bf);
            }
        }
    }

    float inv_lo = 1.f / l_lo, inv_hi = 1.f / l_hi;
    int r = b*SEQ + q0 + wr + lr;
    #pragma unroll
    for (int n9 = 0; n9 < 9; n9++) {
        int c = h*HDIM + n9*8 + 2*lc;
        __half2 p0 = __floats2half2_rn(o[n9].x*inv_lo, o[n9].y*inv_lo);
        __half2 p1 = __floats2half2_rn(o[n9].z*inv_hi, o[n9].w*inv_hi);
        *(__half2*)&g_oh[(size_t)r*HID + c]     = p0;
        *(__half2*)&g_oh[(size_t)(r+8)*HID + c] = p1;
    }
}

// ---------------------------------------------------------------------------
extern "C" void kernel_launch(void* const* d_in, const int* in_sizes, int n_in,
                              void* d_out, int out_size) {
    const float* x      = (const float*)d_in[0];
    const float* c      = (const float*)d_in[1];
    const float* w_ada  = (const float*)d_in[2];
    const float* b_ada  = (const float*)d_in[3];
    const float* w_qkv  = (const float*)d_in[4];
    const float* b_qkv  = (const float*)d_in[5];
    const float* qn_w   = (const float*)d_in[6];
    const float* qn_b   = (const float*)d_in[7];
    const float* kn_w   = (const float*)d_in[8];
    const float* kn_b   = (const float*)d_in[9];
    const float* w_proj = (const float*)d_in[10];
    const float* b_proj = (const float*)d_in[11];
    const float* w_fc1  = (const float*)d_in[12];
    const float* b_fc1  = (const float*)d_in[13];
    const float* w_fc2  = (const float*)d_in[14];
    const float* b_fc2  = (const float*)d_in[15];
    float* out = (float*)d_out;

    float *p_x1;
    __half *p_aih, *p_qkvh, *p_oh, *p_mih, *p_hh;
    __half *p_wqkt, *p_wpt, *p_wf1t, *p_wf2t;
    cudaGetSymbolAddress((void**)&p_x1,   g_x1);
    cudaGetSymbolAddress((void**)&p_aih,  g_aih);
    cudaGetSymbolAddress((void**)&p_qkvh, g_qkvh);
    cudaGetSymbolAddress((void**)&p_oh,   g_oh);
    cudaGetSymbolAddress((void**)&p_mih,  g_mih);
    cudaGetSymbolAddress((void**)&p_hh,   g_hh);
    cudaGetSymbolAddress((void**)&p_wqkt, g_wqkt);
    cudaGetSymbolAddress((void**)&p_wpt,  g_wpt);
    cudaGetSymbolAddress((void**)&p_wf1t, g_wf1t);
    cudaGetSymbolAddress((void**)&p_wf2t, g_wf2t);

    static int attr_set = 0;
    if (!attr_set) {
        cudaFuncSetAttribute(gemm_hf, cudaFuncAttributeMaxDynamicSharedMemorySize, GEMM_SMEM);
        cudaFuncSetAttribute(attn_h, cudaFuncAttributeMaxDynamicSharedMemorySize, ATTN_SMEM);
        attr_set = 1;
    }

    // single stream, fused adaLN (w_ada read once)
    wtrans_kernel<<<dim3(HID/64, DFF/64), 256>>>(w_fc2, p_wf2t, DFF, HID);
    adaln_kernel<<<MOD6/128, 128>>>(c, w_ada, b_ada);
    modulate_kernel<<<MROWS, 288>>>(x, nullptr, 0, 1, -1, nullptr, p_aih);
    wtrans_kernel<<<dim3(3*HID/64, HID/64), 256>>>(w_qkv, p_wqkt, HID, 3*HID);
    gemm_hf<<<dim3(3*HID/128, MROWS/128), 128, GEMM_SMEM>>>(p_aih, p_wqkt, b_qkv, p_qkvh,
                                                            MROWS, 3*HID, HID, 0, 1, nullptr, 0);
    qknorm_kernel<<<MROWS*32/8, 256>>>(qn_w, qn_b, kn_w, kn_b);
    vtrans_kernel<<<dim3(SEQ/64, NHEAD, BB), 128>>>();
    wtrans_kernel<<<dim3(HID/64, HID/64), 256>>>(w_proj, p_wpt, HID, HID);
    wtrans_kernel<<<dim3(DFF/64, HID/64), 256>>>(w_fc1, p_wf1t, HID, DFF);
    attn_h<<<dim3(SEQ/128, NHEAD, BB), 256, ATTN_SMEM>>>();
    // proj with fused residual: x1 = x + g_msa * (o @ w_proj + b)
    gemm_hf<<<dim3(HID/128, MROWS/128), 128, GEMM_SMEM>>>(p_oh, p_wpt, b_proj, p_x1,
                                                          MROWS, HID, HID, 0, 0, x, 2);
    modulate_kernel<<<MROWS, 288>>>(p_x1, nullptr, 3, 4, -1, nullptr, p_mih);
    gemm_hf<<<dim3(DFF/128, MROWS/128), 128, GEMM_SMEM>>>(p_mih, p_wf1t, b_fc1, p_hh,
                                                          MROWS, DFF, HID, 1, 1, nullptr, 0);
    gemm_hf<<<dim3(HID/128, MROWS/128), 128, GEMM_SMEM>>>(p_hh, p_wf2t, b_fc2, out,
                                                          MROWS, HID, DFF, 0, 0, p_x1, 5);
}

// round 13
// speedup vs baseline: 1.0719x; 1.0714x over previous
#include <cuda_runtime.h>
#include <cuda_fp16.h>
#include <math.h>
#include <stdint.h>

#define BB 8
#define SEQ 1024
#define HID 1152
#define NHEAD 16
#define HDIM 72
#define DFF 4608
#define MROWS (BB*SEQ)      // 8192
#define MOD6 (6*HID)        // 6912

// ------------------------- scratch (__device__ globals, no allocs) ----------
__device__ float g_silu_c[BB*HID];
__device__ float g_mod[BB*MOD6];
__device__ float g_x1[MROWS*HID];
// fp16 activations
__device__ __half g_aih[(size_t)MROWS*HID];
__device__ __half g_qkvh[(size_t)MROWS*3*HID];
__device__ __half g_qh[MROWS*HID];
__device__ __half g_kh[MROWS*HID];
__device__ __half g_vth[MROWS*HID];          // V transposed per head: [b][h][d][SEQ]
__device__ __half g_oh[MROWS*HID];
__device__ __half g_mih[(size_t)MROWS*HID];
__device__ __half g_hh[(size_t)MROWS*DFF];
// transposed fp16 weights  Wt[N][K]
__device__ __half g_wqkt[(size_t)3*HID*HID];
__device__ __half g_wpt[(size_t)HID*HID];
__device__ __half g_wf1t[(size_t)DFF*HID];
__device__ __half g_wf2t[(size_t)HID*DFF];

// ------------------------- helpers ------------------------------------------
__device__ __forceinline__ void cp16(void* smem_dst, const void* gsrc) {
    unsigned s = (unsigned)__cvta_generic_to_shared(smem_dst);
    asm volatile("cp.async.cg.shared.global [%0], [%1], 16;" :: "r"(s), "l"(gsrc));
}
__device__ __forceinline__ void mma_f16(float4& d, const uint32_t* a, const uint32_t* b) {
    asm volatile(
        "mma.sync.aligned.m16n8k16.row.col.f32.f16.f16.f32 "
        "{%0,%1,%2,%3}, {%4,%5,%6,%7}, {%8,%9}, {%0,%1,%2,%3};"
        : "+f"(d.x), "+f"(d.y), "+f"(d.z), "+f"(d.w)
        : "r"(a[0]), "r"(a[1]), "r"(a[2]), "r"(a[3]), "r"(b[0]), "r"(b[1]));
}
__device__ __forceinline__ void mma_f16_k8(float4& d, uint32_t a0, uint32_t a1, uint32_t b0) {
    asm volatile(
        "mma.sync.aligned.m16n8k8.row.col.f32.f16.f16.f32 "
        "{%0,%1,%2,%3}, {%4,%5}, {%6}, {%0,%1,%2,%3};"
        : "+f"(d.x), "+f"(d.y), "+f"(d.z), "+f"(d.w)
        : "r"(a0), "r"(a1), "r"(b0));
}
__device__ __forceinline__ void ldsm4(uint32_t& r0, uint32_t& r1, uint32_t& r2, uint32_t& r3,
                                      uint32_t addr) {
    asm volatile("ldmatrix.sync.aligned.m8n8.x4.shared.b16 {%0,%1,%2,%3}, [%4];"
                 : "=r"(r0), "=r"(r1), "=r"(r2), "=r"(r3) : "r"(addr));
}
__device__ __forceinline__ float fast_gelu(float u) {
    float e = __expf(-1.5957691216057308f * fmaf(0.044715f*u*u, u, u));
    return __fdividef(u, 1.f + e);
}

// ------------------------- weight transpose fp32[K][N] -> fp16[N][K] --------
__global__ void __launch_bounds__(256)
wtrans_kernel(const float* __restrict__ in, __half* __restrict__ out, int K, int N) {
    __shared__ float tile[64][65];
    int k0 = blockIdx.y*64, n0 = blockIdx.x*64;
    int t = threadIdx.x;
    #pragma unroll
    for (int i = 0; i < 4; i++) {
        int idx = t + i*256;
        int r = idx >> 4, c = idx & 15;
        float4 v = *(const float4*)&in[(size_t)(k0 + r)*N + n0 + c*4];
        tile[r][c*4+0] = v.x; tile[r][c*4+1] = v.y;
        tile[r][c*4+2] = v.z; tile[r][c*4+3] = v.w;
    }
    __syncthreads();
    #pragma unroll
    for (int i = 0; i < 8; i++) {
        int idx = t + i*256;
        int n = idx >> 5, c = idx & 31;
        __half2 h = __floats2half2_rn(tile[2*c][n], tile[2*c+1][n]);
        *(__half2*)&out[(size_t)(n0 + n)*K + k0 + 2*c] = h;
    }
}

// ------------------------- silu(c) ------------------------------------------
__global__ void silu_kernel(const float* __restrict__ c) {
    int i = blockIdx.x * 256 + threadIdx.x;
    if (i < BB*HID) {
        float s = c[i];
        g_silu_c[i] = s / (1.f + expf(-s));
    }
}

// ------------------------- adaLN (batch-paired accumulators) ----------------
__global__ void adaln_kernel(const float* __restrict__ w_ada,
                             const float* __restrict__ b_ada) {
    int j = blockIdx.x * 256 + threadIdx.x;
    int bp = blockIdx.y;                 // batch pair 0..3
    if (j >= MOD6) return;
    float bj = b_ada[j];
    float a0 = bj, a1 = bj;
    const float* c0 = &g_silu_c[(2*bp)*HID];
    const float* c1 = &g_silu_c[(2*bp + 1)*HID];
    for (int k = 0; k < HID; k++) {
        float w = w_ada[(size_t)k*MOD6 + j];
        a0 = fmaf(c0[k], w, a0);
        a1 = fmaf(c1[k], w, a1);
    }
    g_mod[(2*bp)*MOD6 + j]     = a0;
    g_mod[(2*bp + 1)*MOD6 + j] = a1;
}

// --------------- fused (optional residual+gate) + LN + modulate -> fp16 -----
__global__ void __launch_bounds__(288)
modulate_kernel(const float* __restrict__ x, const float* __restrict__ res,
                int sh_seg, int sc_seg, int g_seg,
                float* __restrict__ x1_out, __half* __restrict__ mi_out) {
    int r = blockIdx.x, b = r / SEQ, t = threadIdx.x;
    const float* modb = &g_mod[b*MOD6];

    float4 val = *(const float4*)&x[(size_t)r*HID + t*4];
    if (res) {
        float4 rv = *(const float4*)&res[(size_t)r*HID + t*4];
        float4 gv = *(const float4*)&modb[g_seg*HID + t*4];
        val.x = fmaf(gv.x, rv.x, val.x); val.y = fmaf(gv.y, rv.y, val.y);
        val.z = fmaf(gv.z, rv.z, val.z); val.w = fmaf(gv.w, rv.w, val.w);
    }
    if (x1_out) *(float4*)&x1_out[(size_t)r*HID + t*4] = val;

    float s  = val.x + val.y + val.z + val.w;
    float ss = val.x*val.x + val.y*val.y + val.z*val.z + val.w*val.w;
    int lane = t & 31, wid = t >> 5;
    #pragma unroll
    for (int o = 16; o; o >>= 1) {
        s  += __shfl_xor_sync(0xffffffffu, s, o);
        ss += __shfl_xor_sync(0xffffffffu, ss, o);
    }
    __shared__ float sh1[9], sh2[9];
    if (lane == 0) { sh1[wid] = s; sh2[wid] = ss; }
    __syncthreads();
    if (t == 0) {
        float a = 0.f, bb = 0.f;
        #pragma unroll
        for (int i = 0; i < 9; i++) { a += sh1[i]; bb += sh2[i]; }
        sh1[0] = a; sh2[0] = bb;
    }
    __syncthreads();
    float mean = sh1[0] * (1.f/HID);
    float var  = sh2[0] * (1.f/HID) - mean*mean;
    float inv  = rsqrtf(var + 1e-6f);

    float4 sc4 = *(const float4*)&modb[sc_seg*HID + t*4];
    float4 sh4 = *(const float4*)&modb[sh_seg*HID + t*4];
    float y0 = (val.x - mean)*inv*(1.f + sc4.x) + sh4.x;
    float y1 = (val.y - mean)*inv*(1.f + sc4.y) + sh4.y;
    float y2 = (val.z - mean)*inv*(1.f + sc4.z) + sh4.z;
    float y3 = (val.w - mean)*inv*(1.f + sc4.w) + sh4.w;
    __half2 h0 = __floats2half2_rn(y0, y1);
    __half2 h1 = __floats2half2_rn(y2, y3);
    uint2 pk; pk.x = *(uint32_t*)&h0; pk.y = *(uint32_t*)&h1;
    *(uint2*)&mi_out[(size_t)r*HID + t*4] = pk;
}

// ------------------------- fp16 HMMA GEMM (ldmatrix + 3-stage) ---------------
#define AW 36
#define TILE_W (128*AW)
#define GEMM_SMEM (6*TILE_W*4)   // 108 KB

__global__ void __launch_bounds__(128)
gemm_hf(const __half* __restrict__ A, const __half* __restrict__ Bt,
        const float* __restrict__ bias, void* __restrict__ Cout,
        int M, int N, int K, int act, int outH,
        const float* __restrict__ resid, int gate_seg) {
    extern __shared__ uint32_t smw[];
    uint32_t smw_b = (uint32_t)__cvta_generic_to_shared(smw);

    int tid = threadIdx.x, lane = tid & 31, wid = tid >> 5;
    int wm = wid >> 1, wn = wid & 1;
    int row0 = blockIdx.y * 128, col0 = blockIdx.x * 128;
    int lr = lane >> 2, lc = lane & 3;
    int g = lane >> 3, lrow = lane & 7;
    int a_row = wm*64 + (g & 1)*8 + lrow;
    int a_wc  = (g >> 1)*4;
    int b_row = wn*64 + (g >> 1)*8 + lrow;
    int b_wc  = (g & 1)*4;

    float4 acc[4][8];
    #pragma unroll
    for (int i = 0; i < 4; i++)
        #pragma unroll
        for (int j = 0; j < 8; j++) acc[i][j] = make_float4(0.f,0.f,0.f,0.f);

    int KT = K >> 6;

    auto load_stage = [&](int kt, int buf) {
        const __half* gA = A  + (size_t)row0*K + kt*64;
        const __half* gB = Bt + (size_t)col0*K + kt*64;
        uint32_t* as = smw + buf*2*TILE_W;
        uint32_t* bs = as + TILE_W;
        #pragma unroll
        for (int i = 0; i < 8; i++) {
            int chunk = tid + i*128;
            int r = chunk >> 3, c = chunk & 7;
            cp16(&as[r*AW + c*4], gA + (size_t)r*K + c*8);
            cp16(&bs[r*AW + c*4], gB + (size_t)r*K + c*8);
        }
        asm volatile("cp.async.commit_group;");
    };

    load_stage(0, 0);
    if (KT > 1) load_stage(1, 1);

    for (int kt = 0; kt < KT; kt++) {
        if (kt < KT - 1) asm volatile("cp.async.wait_group 1;");
        else             asm volatile("cp.async.wait_group 0;");
        __syncthreads();
        if (kt + 2 < KT) load_stage(kt + 2, (kt + 2) % 3);

        int buf = kt % 3;
        uint32_t as_b = smw_b + buf*2*TILE_W*4;
        uint32_t bs_b = as_b + TILE_W*4;
        #pragma unroll
        for (int k16 = 0; k16 < 4; k16++) {
            uint32_t af[4][4];
            #pragma unroll
            for (int mi = 0; mi < 4; mi++)
                ldsm4(af[mi][0], af[mi][1], af[mi][2], af[mi][3],
                      as_b + (uint32_t)(((a_row + mi*16)*AW) + k16*8 + a_wc)*4);
            uint32_t bf[8][2];
            #pragma unroll
            for (int njp = 0; njp < 4; njp++)
                ldsm4(bf[2*njp][0], bf[2*njp][1], bf[2*njp+1][0], bf[2*njp+1][1],
                      bs_b + (uint32_t)(((b_row + njp*16)*AW) + k16*8 + b_wc)*4);
            #pragma unroll
            for (int mi = 0; mi < 4; mi++)
                #pragma unroll
                for (int nj = 0; nj < 8; nj++)
                    mma_f16(acc[mi][nj], af[mi], bf[nj]);
        }
        __syncthreads();
    }

    #pragma unroll
    for (int mi = 0; mi < 4; mi++) {
        #pragma unroll
        for (int nj = 0; nj < 8; nj++) {
            int r = row0 + wm*64 + mi*16 + lr;
            int c = col0 + wn*64 + nj*8 + 2*lc;
            float v[4] = {acc[mi][nj].x, acc[mi][nj].y, acc[mi][nj].z, acc[mi][nj].w};
            float b0 = bias[c], b1 = bias[c+1];
            v[0] += b0; v[1] += b1; v[2] += b0; v[3] += b1;
            if (act == 1) {
                #pragma unroll
                for (int q = 0; q < 4; q++) v[q] = fast_gelu(v[q]);
            }
            if (outH) {
                __half* Cb = (__half*)Cout;
                __half2 p0 = __floats2half2_rn(v[0], v[1]);
                __half2 p1 = __floats2half2_rn(v[2], v[3]);
                *(__half2*)&Cb[(size_t)r*N + c]     = p0;
                *(__half2*)&Cb[(size_t)(r+8)*N + c] = p1;
            } else {
                float* Cf = (float*)Cout;
                if (resid) {
                    int b = r / SEQ;
                    float g0 = g_mod[b*MOD6 + gate_seg*HID + c];
                    float g1 = g_mod[b*MOD6 + gate_seg*HID + c + 1];
                    v[0] = resid[(size_t)r*N + c]     + g0*v[0];
                    v[1] = resid[(size_t)r*N + c + 1] + g1*v[1];
                    v[2] = resid[(size_t)(r+8)*N + c]     + g0*v[2];
                    v[3] = resid[(size_t)(r+8)*N + c + 1] + g1*v[3];
                }
                *(float2*)&Cf[(size_t)r*N + c]     = make_float2(v[0], v[1]);
                *(float2*)&Cf[(size_t)(r+8)*N + c] = make_float2(v[2], v[3]);
            }
        }
    }
}

// ------------------------- qk-norm (q,k only) -> [B,NH,N,HD] fp16 -----------
__global__ void qknorm_kernel(const float* __restrict__ qn_w, const float* __restrict__ qn_b,
                              const float* __restrict__ kn_w, const float* __restrict__ kn_b) {
    int id = blockIdx.x * 8 + (threadIdx.x >> 5);
    if (id >= MROWS*32) return;
    int lane = threadIdx.x & 31;
    int r = id >> 5;
    int rem = id & 31;
    int w = rem >> 4;      // 0=q, 1=k
    int h = rem & 15;

    const __half* src = &g_qkvh[(size_t)r*3456 + w*1152 + h*72];
    float v0 = __half2float(src[lane]);
    float v1 = __half2float(src[lane + 32]);
    float v2 = (lane < 8) ? __half2float(src[lane + 64]) : 0.f;

    int b = r / SEQ, n = r % SEQ;
    __half* dst = (w == 0 ? g_qh : g_kh)
                 + (((size_t)(b*NHEAD + h)*SEQ + n)*HDIM);

    float s = v0 + v1 + v2;
    float ss = v0*v0 + v1*v1 + v2*v2;
    #pragma unroll
    for (int o = 16; o; o >>= 1) {
        s  += __shfl_xor_sync(0xffffffffu, s, o);
        ss += __shfl_xor_sync(0xffffffffu, ss, o);
    }
    float mean = s * (1.f/72.f);
    float var  = ss * (1.f/72.f) - mean*mean;
    float inv  = rsqrtf(var + 1e-5f);
    const float* ww = (w == 0) ? qn_w : kn_w;
    const float* wb = (w == 0) ? qn_b : kn_b;
    dst[lane]      = __float2half((v0 - mean)*inv*ww[lane]      + wb[lane]);
    dst[lane + 32] = __float2half((v1 - mean)*inv*ww[lane + 32] + wb[lane + 32]);
    if (lane < 8)
        dst[lane + 64] = __float2half((v2 - mean)*inv*ww[lane + 64] + wb[lane + 64]);
}

// ------------------------- V transpose: qkv v-slice -> [b][h][d][SEQ] -------
__global__ void __launch_bounds__(128) vtrans_kernel() {
    __shared__ uint32_t tile[64*37];   // stride 37 words = 74 halves
    int kt = blockIdx.x, h = blockIdx.y, b = blockIdx.z;
    int t = threadIdx.x;
    const uint32_t* src32 = (const uint32_t*)g_qkvh;

    for (int i = t; i < 64*36; i += 128) {
        int key = i / 36, w = i % 36;
        size_t off = ((size_t)(b*SEQ + kt*64 + key)*3456 + 2304 + h*72) / 2 + w;
        tile[key*37 + w] = src32[off];
    }
    __syncthreads();
    const __half* tileh = (const __half*)tile;
    uint32_t* dst32 = (uint32_t*)g_vth;
    for (int i = t; i < 72*32; i += 128) {
        int d = i / 32, w2 = i % 32;
        __half2 p;
        p.x = tileh[(2*w2)*74 + d];
        p.y = tileh[(2*w2 + 1)*74 + d];
        dst32[((size_t)((b*NHEAD + h)*HDIM + d)*SEQ)/2 + kt*32 + w2] = *(uint32_t*)&p;
    }
}

// ------------------------- fp16 tensor-core flash attention -----------------
#define AT_QW (128*36)
#define AT_KW (64*36)
#define AT_VW (72*36)
#define ATTN_SMEM ((AT_QW + 2*AT_KW + 2*AT_VW)*4)   // 57.6 KB

__global__ void __launch_bounds__(256) attn_h() {
    extern __shared__ uint32_t smw[];
    uint32_t* Qs = smw;
    uint32_t* Kb = Qs + AT_QW;
    uint32_t* Vb = Kb + 2*AT_KW;

    int b = blockIdx.z, h = blockIdx.y, q0 = blockIdx.x*128;
    int tid = threadIdx.x, lane = tid & 31, wid = tid >> 5;
    int lr = lane >> 2, lc = lane & 3;
    int wr = wid * 16;
    size_t base = (size_t)(b*NHEAD + h) * SEQ * HDIM;
    const __half* vbase = &g_vth[(size_t)(b*NHEAD + h) * HDIM * SEQ];
    const float scale = 0.11785113019775793f;

    auto load_stage = [&](int t, int buf) {
        const __half* kg = &g_kh[base + (size_t)(t*64)*HDIM];
        for (int i = tid; i < 576; i += 256) {
            int r = i / 9, c = i % 9;
            cp16(&Kb[buf*AT_KW + r*36 + c*4], kg + r*HDIM + c*8);
        }
        const __half* vg = vbase + t*64;
        for (int i = tid; i < 576; i += 256) {
            int d = i >> 3, c = i & 7;
            cp16(&Vb[buf*AT_VW + d*36 + c*4], vg + (size_t)d*SEQ + c*8);
        }
        asm volatile("cp.async.commit_group;");
    };

    {
        const uint4* qg = (const uint4*)&g_qh[base + (size_t)q0*HDIM];
        for (int i = tid; i < 128*9; i += 256) {
            int r = i / 9, c = i % 9;
            *(uint4*)&Qs[r*36 + c*4] = qg[i];
        }
    }
    load_stage(0, 0);

    float4 o[9];
    #pragma unroll
    for (int i = 0; i < 9; i++) o[i] = make_float4(0.f,0.f,0.f,0.f);
    float m_lo = -INFINITY, m_hi = -INFINITY, l_lo = 0.f, l_hi = 0.f;

    for (int t = 0; t < 16; t++) {
        asm volatile("cp.async.wait_group 0;");
        __syncthreads();
        if (t + 1 < 16) load_stage(t + 1, (t + 1) & 1);
        int buf = t & 1;
        const uint32_t* Ks = &Kb[buf*AT_KW];
        const uint32_t* Vt = &Vb[buf*AT_VW];

        float4 sc[8];
        #pragma unroll
        for (int i = 0; i < 8; i++) sc[i] = make_float4(0.f,0.f,0.f,0.f);
        #pragma unroll
        for (int k16 = 0; k16 < 4; k16++) {
            int kw = k16*8 + lc;
            uint32_t af[4];
            af[0] = Qs[(wr+lr)*36 + kw];
            af[1] = Qs[(wr+8+lr)*36 + kw];
            af[2] = Qs[(wr+lr)*36 + kw + 4];
            af[3] = Qs[(wr+8+lr)*36 + kw + 4];
            #pragma unroll
            for (int nj = 0; nj < 8; nj++) {
                int cc = nj*8 + lr;
                uint32_t bf[2] = {Ks[cc*36 + kw], Ks[cc*36 + kw + 4]};
                mma_f16(sc[nj], af, bf);
            }
        }
        {
            int kw = 32 + lc;
            uint32_t a0 = Qs[(wr+lr)*36 + kw];
            uint32_t a1 = Qs[(wr+8+lr)*36 + kw];
            #pragma unroll
            for (int nj = 0; nj < 8; nj++) {
                int cc = nj*8 + lr;
                mma_f16_k8(sc[nj], a0, a1, Ks[cc*36 + kw]);
            }
        }

        float tmax_lo = -INFINITY, tmax_hi = -INFINITY;
        #pragma unroll
        for (int nj = 0; nj < 8; nj++) {
            sc[nj].x *= scale; sc[nj].y *= scale; sc[nj].z *= scale; sc[nj].w *= scale;
            tmax_lo = fmaxf(tmax_lo, fmaxf(sc[nj].x, sc[nj].y));
            tmax_hi = fmaxf(tmax_hi, fmaxf(sc[nj].z, sc[nj].w));
        }
        tmax_lo = fmaxf(tmax_lo, __shfl_xor_sync(0xffffffffu, tmax_lo, 1));
        tmax_lo = fmaxf(tmax_lo, __shfl_xor_sync(0xffffffffu, tmax_lo, 2));
        tmax_hi = fmaxf(tmax_hi, __shfl_xor_sync(0xffffffffu, tmax_hi, 1));
        tmax_hi = fmaxf(tmax_hi, __shfl_xor_sync(0xffffffffu, tmax_hi, 2));

        float mn_lo = fmaxf(m_lo, tmax_lo);
        float mn_hi = fmaxf(m_hi, tmax_hi);
        float corr_lo = __expf(m_lo - mn_lo);
        float corr_hi = __expf(m_hi - mn_hi);
        l_lo *= corr_lo; l_hi *= corr_hi;
        #pragma unroll
        for (int i = 0; i < 9; i++) {
            o[i].x *= corr_lo; o[i].y *= corr_lo;
            o[i].z *= corr_hi; o[i].w *= corr_hi;
        }
        uint32_t ph[8][2];
        float sum_lo = 0.f, sum_hi = 0.f;
        #pragma unroll
        for (int nj = 0; nj < 8; nj++) {
            float px = __expf(sc[nj].x - mn_lo);
            float py = __expf(sc[nj].y - mn_lo);
            float pz = __expf(sc[nj].z - mn_hi);
            float pw = __expf(sc[nj].w - mn_hi);
            sum_lo += px + py; sum_hi += pz + pw;
            __half2 plo = __floats2half2_rn(px, py);
            __half2 phi = __floats2half2_rn(pz, pw);
            ph[nj][0] = *(uint32_t*)&plo;
            ph[nj][1] = *(uint32_t*)&phi;
        }
        sum_lo += __shfl_xor_sync(0xffffffffu, sum_lo, 1);
        sum_lo += __shfl_xor_sync(0xffffffffu, sum_lo, 2);
        sum_hi += __shfl_xor_sync(0xffffffffu, sum_hi, 1);
        sum_hi += __shfl_xor_sync(0xffffffffu, sum_hi, 2);
        l_lo += sum_lo; l_hi += sum_hi;
        m_lo = mn_lo; m_hi = mn_hi;

        #pragma unroll
        for (int k16 = 0; k16 < 4; k16++) {
            int kw = k16*8 + lc;
            uint32_t af[4];
            af[0] = ph[2*k16][0];
            af[1] = ph[2*k16][1];
            af[2] = ph[2*k16+1][0];
            af[3] = ph[2*k16+1][1];
            #pragma unroll
            for (int n9 = 0; n9 < 9; n9++) {
                int cc = n9*8 + lr;
                uint32_t bf[2] = {Vt[cc*36 + kw], Vt[cc*36 + kw + 4]};
                mma_f16(o[n9], af, bf);
            }
        }
    }

    float inv_lo = 1.f / l_lo, inv_hi = 1.f / l_hi;
    int r = b*SEQ + q0 + wr + lr;
    #pragma unroll
    for (int n9 = 0; n9 < 9; n9++) {
        int c = h*HDIM + n9*8 + 2*lc;
        __half2 p0 = __floats2half2_rn(o[n9].x*inv_lo, o[n9].y*inv_lo);
        __half2 p1 = __floats2half2_rn(o[n9].z*inv_hi, o[n9].w*inv_hi);
        *(__half2*)&g_oh[(size_t)r*HID + c]     = p0;
        *(__half2*)&g_oh[(size_t)(r+8)*HID + c] = p1;
    }
}

// ---------------------------------------------------------------------------
extern "C" void kernel_launch(void* const* d_in, const int* in_sizes, int n_in,
                              void* d_out, int out_size) {
    const float* x      = (const float*)d_in[0];
    const float* c      = (const float*)d_in[1];
    const float* w_ada  = (const float*)d_in[2];
    const float* b_ada  = (const float*)d_in[3];
    const float* w_qkv  = (const float*)d_in[4];
    const float* b_qkv  = (const float*)d_in[5];
    const float* qn_w   = (const float*)d_in[6];
    const float* qn_b   = (const float*)d_in[7];
    const float* kn_w   = (const float*)d_in[8];
    const float* kn_b   = (const float*)d_in[9];
    const float* w_proj = (const float*)d_in[10];
    const float* b_proj = (const float*)d_in[11];
    const float* w_fc1  = (const float*)d_in[12];
    const float* b_fc1  = (const float*)d_in[13];
    const float* w_fc2  = (const float*)d_in[14];
    const float* b_fc2  = (const float*)d_in[15];
    float* out = (float*)d_out;

    float *p_x1;
    __half *p_aih, *p_qkvh, *p_oh, *p_mih, *p_hh;
    __half *p_wqkt, *p_wpt, *p_wf1t, *p_wf2t;
    cudaGetSymbolAddress((void**)&p_x1,   g_x1);
    cudaGetSymbolAddress((void**)&p_aih,  g_aih);
    cudaGetSymbolAddress((void**)&p_qkvh, g_qkvh);
    cudaGetSymbolAddress((void**)&p_oh,   g_oh);
    cudaGetSymbolAddress((void**)&p_mih,  g_mih);
    cudaGetSymbolAddress((void**)&p_hh,   g_hh);
    cudaGetSymbolAddress((void**)&p_wqkt, g_wqkt);
    cudaGetSymbolAddress((void**)&p_wpt,  g_wpt);
    cudaGetSymbolAddress((void**)&p_wf1t, g_wf1t);
    cudaGetSymbolAddress((void**)&p_wf2t, g_wf2t);

    static int attr_set = 0;
    if (!attr_set) {
        cudaFuncSetAttribute(gemm_hf, cudaFuncAttributeMaxDynamicSharedMemorySize, GEMM_SMEM);
        cudaFuncSetAttribute(attn_h, cudaFuncAttributeMaxDynamicSharedMemorySize, ATTN_SMEM);
        attr_set = 1;
    }

    wtrans_kernel<<<dim3(HID/64, DFF/64), 256>>>(w_fc2, p_wf2t, DFF, HID);
    silu_kernel<<<(BB*HID + 255)/256, 256>>>(c);
    adaln_kernel<<<dim3(MOD6/256, BB/2), 256>>>(w_ada, b_ada);
    modulate_kernel<<<MROWS, 288>>>(x, nullptr, 0, 1, -1, nullptr, p_aih);
    wtrans_kernel<<<dim3(3*HID/64, HID/64), 256>>>(w_qkv, p_wqkt, HID, 3*HID);
    gemm_hf<<<dim3(3*HID/128, MROWS/128), 128, GEMM_SMEM>>>(p_aih, p_wqkt, b_qkv, p_qkvh,
                                                            MROWS, 3*HID, HID, 0, 1, nullptr, 0);
    qknorm_kernel<<<MROWS*32/8, 256>>>(qn_w, qn_b, kn_w, kn_b);
    vtrans_kernel<<<dim3(SEQ/64, NHEAD, BB), 128>>>();
    wtrans_kernel<<<dim3(HID/64, HID/64), 256>>>(w_proj, p_wpt, HID, HID);
    wtrans_kernel<<<dim3(DFF/64, HID/64), 256>>>(w_fc1, p_wf1t, HID, DFF);
    attn_h<<<dim3(SEQ/128, NHEAD, BB), 256, ATTN_SMEM>>>();
    // proj with fused residual: x1 = x + g_msa * (o @ w_proj + b)
    gemm_hf<<<dim3(HID/128, MROWS/128), 128, GEMM_SMEM>>>(p_oh, p_wpt, b_proj, p_x1,
                                                          MROWS, HID, HID, 0, 0, x, 2);
    modulate_kernel<<<MROWS, 288>>>(p_x1, nullptr, 3, 4, -1, nullptr, p_mih);
    gemm_hf<<<dim3(DFF/128, MROWS/128), 128, GEMM_SMEM>>>(p_mih, p_wf1t, b_fc1, p_hh,
                                                          MROWS, DFF, HID, 1, 1, nullptr, 0);
    gemm_hf<<<dim3(HID/128, MROWS/128), 128, GEMM_SMEM>>>(p_hh, p_wf2t, b_fc2, out,
                                                          MROWS, HID, DFF, 0, 0, p_x1, 5);
}

// round 14
// speedup vs baseline: 1.1316x; 1.0556x over previous
#include <cuda_runtime.h>
#include <cuda_fp16.h>
#include <math.h>
#include <stdint.h>

#define BB 8
#define SEQ 1024
#define HID 1152
#define NHEAD 16
#define HDIM 72
#define DFF 4608
#define MROWS (BB*SEQ)      // 8192
#define MOD6 (6*HID)        // 6912

// ------------------------- scratch (__device__ globals, no allocs) ----------
__device__ float g_mod[BB*MOD6];
__device__ float g_x1[MROWS*HID];
// fp16 activations
__device__ __half g_aih[(size_t)MROWS*HID];
__device__ __half g_qkvh[(size_t)MROWS*3*HID];
__device__ __half g_qh[MROWS*HID];
__device__ __half g_kh[MROWS*HID];
__device__ __half g_vth[MROWS*HID];          // V transposed per head: [b][h][d][SEQ]
__device__ __half g_oh[MROWS*HID];
__device__ __half g_mih[(size_t)MROWS*HID];
__device__ __half g_hh[(size_t)MROWS*DFF];
// transposed fp16 weights  Wt[N][K]
__device__ __half g_wqkt[(size_t)3*HID*HID];
__device__ __half g_wpt[(size_t)HID*HID];
__device__ __half g_wf1t[(size_t)DFF*HID];
__device__ __half g_wf2t[(size_t)HID*DFF];

// ------------------------- helpers ------------------------------------------
__device__ __forceinline__ void cp16(void* smem_dst, const void* gsrc) {
    unsigned s = (unsigned)__cvta_generic_to_shared(smem_dst);
    asm volatile("cp.async.cg.shared.global [%0], [%1], 16;" :: "r"(s), "l"(gsrc));
}
__device__ __forceinline__ void mma_f16(float4& d, const uint32_t* a, const uint32_t* b) {
    asm volatile(
        "mma.sync.aligned.m16n8k16.row.col.f32.f16.f16.f32 "
        "{%0,%1,%2,%3}, {%4,%5,%6,%7}, {%8,%9}, {%0,%1,%2,%3};"
        : "+f"(d.x), "+f"(d.y), "+f"(d.z), "+f"(d.w)
        : "r"(a[0]), "r"(a[1]), "r"(a[2]), "r"(a[3]), "r"(b[0]), "r"(b[1]));
}
__device__ __forceinline__ void mma_f16_k8(float4& d, uint32_t a0, uint32_t a1, uint32_t b0) {
    asm volatile(
        "mma.sync.aligned.m16n8k8.row.col.f32.f16.f16.f32 "
        "{%0,%1,%2,%3}, {%4,%5}, {%6}, {%0,%1,%2,%3};"
        : "+f"(d.x), "+f"(d.y), "+f"(d.z), "+f"(d.w)
        : "r"(a0), "r"(a1), "r"(b0));
}
__device__ __forceinline__ void ldsm4(uint32_t& r0, uint32_t& r1, uint32_t& r2, uint32_t& r3,
                                      uint32_t addr) {
    asm volatile("ldmatrix.sync.aligned.m8n8.x4.shared.b16 {%0,%1,%2,%3}, [%4];"
                 : "=r"(r0), "=r"(r1), "=r"(r2), "=r"(r3) : "r"(addr));
}
__device__ __forceinline__ float fast_gelu(float u) {
    float e = __expf(-1.5957691216057308f * fmaf(0.044715f*u*u, u, u));
    return __fdividef(u, 1.f + e);
}

// ------------------------- weight transpose fp32[K][N] -> fp16[N][K] --------
__global__ void __launch_bounds__(256)
wtrans_kernel(const float* __restrict__ in, __half* __restrict__ out, int K, int N) {
    __shared__ float tile[64][65];
    int k0 = blockIdx.y*64, n0 = blockIdx.x*64;
    int t = threadIdx.x;
    #pragma unroll
    for (int i = 0; i < 4; i++) {
        int idx = t + i*256;
        int r = idx >> 4, c = idx & 15;
        float4 v = *(const float4*)&in[(size_t)(k0 + r)*N + n0 + c*4];
        tile[r][c*4+0] = v.x; tile[r][c*4+1] = v.y;
        tile[r][c*4+2] = v.z; tile[r][c*4+3] = v.w;
    }
    __syncthreads();
    #pragma unroll
    for (int i = 0; i < 8; i++) {
        int idx = t + i*256;
        int n = idx >> 5, c = idx & 31;
        __half2 h = __floats2half2_rn(tile[2*c][n], tile[2*c+1][n]);
        *(__half2*)&out[(size_t)(n0 + n)*K + k0 + 2*c] = h;
    }
}

// ---------------- adaLN per-batch (silu folded in; max parallelism) ---------
// grid (MOD6/256, BB), 256 threads. Block computes silu(c[b]) into smem once,
// then each thread owns one output column j of g_mod[b].
__global__ void __launch_bounds__(256)
adaln_kernel(const float* __restrict__ c, const float* __restrict__ w_ada,
             const float* __restrict__ b_ada) {
    __shared__ float sc[HID];
    int b = blockIdx.y;
    int tid = threadIdx.x;
    for (int i = tid; i < HID; i += 256) {
        float s = c[b*HID + i];
        sc[i] = s / (1.f + expf(-s));
    }
    __syncthreads();
    int j = blockIdx.x*256 + tid;
    float acc = b_ada[j];
    for (int k = 0; k < HID; k++)
        acc = fmaf(sc[k], w_ada[(size_t)k*MOD6 + j], acc);
    g_mod[b*MOD6 + j] = acc;
}

// --------------- fused (optional residual+gate) + LN + modulate -> fp16 -----
__global__ void __launch_bounds__(288)
modulate_kernel(const float* __restrict__ x, const float* __restrict__ res,
                int sh_seg, int sc_seg, int g_seg,
                float* __restrict__ x1_out, __half* __restrict__ mi_out) {
    int r = blockIdx.x, b = r / SEQ, t = threadIdx.x;
    const float* modb = &g_mod[b*MOD6];

    float4 val = *(const float4*)&x[(size_t)r*HID + t*4];
    if (res) {
        float4 rv = *(const float4*)&res[(size_t)r*HID + t*4];
        float4 gv = *(const float4*)&modb[g_seg*HID + t*4];
        val.x = fmaf(gv.x, rv.x, val.x); val.y = fmaf(gv.y, rv.y, val.y);
        val.z = fmaf(gv.z, rv.z, val.z); val.w = fmaf(gv.w, rv.w, val.w);
    }
    if (x1_out) *(float4*)&x1_out[(size_t)r*HID + t*4] = val;

    float s  = val.x + val.y + val.z + val.w;
    float ss = val.x*val.x + val.y*val.y + val.z*val.z + val.w*val.w;
    int lane = t & 31, wid = t >> 5;
    #pragma unroll
    for (int o = 16; o; o >>= 1) {
        s  += __shfl_xor_sync(0xffffffffu, s, o);
        ss += __shfl_xor_sync(0xffffffffu, ss, o);
    }
    __shared__ float sh1[9], sh2[9];
    if (lane == 0) { sh1[wid] = s; sh2[wid] = ss; }
    __syncthreads();
    if (t == 0) {
        float a = 0.f, bb = 0.f;
        #pragma unroll
        for (int i = 0; i < 9; i++) { a += sh1[i]; bb += sh2[i]; }
        sh1[0] = a; sh2[0] = bb;
    }
    __syncthreads();
    float mean = sh1[0] * (1.f/HID);
    float var  = sh2[0] * (1.f/HID) - mean*mean;
    float inv  = rsqrtf(var + 1e-6f);

    float4 sc4 = *(const float4*)&modb[sc_seg*HID + t*4];
    float4 sh4 = *(const float4*)&modb[sh_seg*HID + t*4];
    float y0 = (val.x - mean)*inv*(1.f + sc4.x) + sh4.x;
    float y1 = (val.y - mean)*inv*(1.f + sc4.y) + sh4.y;
    float y2 = (val.z - mean)*inv*(1.f + sc4.z) + sh4.z;
    float y3 = (val.w - mean)*inv*(1.f + sc4.w) + sh4.w;
    __half2 h0 = __floats2half2_rn(y0, y1);
    __half2 h1 = __floats2half2_rn(y2, y3);
    uint2 pk; pk.x = *(uint32_t*)&h0; pk.y = *(uint32_t*)&h1;
    *(uint2*)&mi_out[(size_t)r*HID + t*4] = pk;
}

// ------------------------- fp16 HMMA GEMM (ldmatrix + 3-stage) ---------------
#define AW 36
#define TILE_W (128*AW)
#define GEMM_SMEM (6*TILE_W*4)   // 108 KB

__global__ void __launch_bounds__(128)
gemm_hf(const __half* __restrict__ A, const __half* __restrict__ Bt,
        const float* __restrict__ bias, void* __restrict__ Cout,
        int M, int N, int K, int act, int outH,
        const float* __restrict__ resid, int gate_seg) {
    extern __shared__ uint32_t smw[];
    uint32_t smw_b = (uint32_t)__cvta_generic_to_shared(smw);

    int tid = threadIdx.x, lane = tid & 31, wid = tid >> 5;
    int wm = wid >> 1, wn = wid & 1;
    int row0 = blockIdx.y * 128, col0 = blockIdx.x * 128;
    int lr = lane >> 2, lc = lane & 3;
    int g = lane >> 3, lrow = lane & 7;
    int a_row = wm*64 + (g & 1)*8 + lrow;
    int a_wc  = (g >> 1)*4;
    int b_row = wn*64 + (g >> 1)*8 + lrow;
    int b_wc  = (g & 1)*4;

    float4 acc[4][8];
    #pragma unroll
    for (int i = 0; i < 4; i++)
        #pragma unroll
        for (int j = 0; j < 8; j++) acc[i][j] = make_float4(0.f,0.f,0.f,0.f);

    int KT = K >> 6;

    auto load_stage = [&](int kt, int buf) {
        const __half* gA = A  + (size_t)row0*K + kt*64;
        const __half* gB = Bt + (size_t)col0*K + kt*64;
        uint32_t* as = smw + buf*2*TILE_W;
        uint32_t* bs = as + TILE_W;
        #pragma unroll
        for (int i = 0; i < 8; i++) {
            int chunk = tid + i*128;
            int r = chunk >> 3, c = chunk & 7;
            cp16(&as[r*AW + c*4], gA + (size_t)r*K + c*8);
            cp16(&bs[r*AW + c*4], gB + (size_t)r*K + c*8);
        }
        asm volatile("cp.async.commit_group;");
    };

    load_stage(0, 0);
    if (KT > 1) load_stage(1, 1);

    for (int kt = 0; kt < KT; kt++) {
        if (kt < KT - 1) asm volatile("cp.async.wait_group 1;");
        else             asm volatile("cp.async.wait_group 0;");
        __syncthreads();
        if (kt + 2 < KT) load_stage(kt + 2, (kt + 2) % 3);

        int buf = kt % 3;
        uint32_t as_b = smw_b + buf*2*TILE_W*4;
        uint32_t bs_b = as_b + TILE_W*4;
        #pragma unroll
        for (int k16 = 0; k16 < 4; k16++) {
            uint32_t af[4][4];
            #pragma unroll
            for (int mi = 0; mi < 4; mi++)
                ldsm4(af[mi][0], af[mi][1], af[mi][2], af[mi][3],
                      as_b + (uint32_t)(((a_row + mi*16)*AW) + k16*8 + a_wc)*4);
            uint32_t bf[8][2];
            #pragma unroll
            for (int njp = 0; njp < 4; njp++)
                ldsm4(bf[2*njp][0], bf[2*njp][1], bf[2*njp+1][0], bf[2*njp+1][1],
                      bs_b + (uint32_t)(((b_row + njp*16)*AW) + k16*8 + b_wc)*4);
            #pragma unroll
            for (int mi = 0; mi < 4; mi++)
                #pragma unroll
                for (int nj = 0; nj < 8; nj++)
                    mma_f16(acc[mi][nj], af[mi], bf[nj]);
        }
        __syncthreads();
    }

    #pragma unroll
    for (int mi = 0; mi < 4; mi++) {
        #pragma unroll
        for (int nj = 0; nj < 8; nj++) {
            int r = row0 + wm*64 + mi*16 + lr;
            int c = col0 + wn*64 + nj*8 + 2*lc;
            float v[4] = {acc[mi][nj].x, acc[mi][nj].y, acc[mi][nj].z, acc[mi][nj].w};
            float b0 = bias[c], b1 = bias[c+1];
            v[0] += b0; v[1] += b1; v[2] += b0; v[3] += b1;
            if (act == 1) {
                #pragma unroll
                for (int q = 0; q < 4; q++) v[q] = fast_gelu(v[q]);
            }
            if (outH) {
                __half* Cb = (__half*)Cout;
                __half2 p0 = __floats2half2_rn(v[0], v[1]);
                __half2 p1 = __floats2half2_rn(v[2], v[3]);
                *(__half2*)&Cb[(size_t)r*N + c]     = p0;
                *(__half2*)&Cb[(size_t)(r+8)*N + c] = p1;
            } else {
                float* Cf = (float*)Cout;
                if (resid) {
                    int b = r / SEQ;
                    float g0 = g_mod[b*MOD6 + gate_seg*HID + c];
                    float g1 = g_mod[b*MOD6 + gate_seg*HID + c + 1];
                    v[0] = resid[(size_t)r*N + c]     + g0*v[0];
                    v[1] = resid[(size_t)r*N + c + 1] + g1*v[1];
                    v[2] = resid[(size_t)(r+8)*N + c]     + g0*v[2];
                    v[3] = resid[(size_t)(r+8)*N + c + 1] + g1*v[3];
                }
                *(float2*)&Cf[(size_t)r*N + c]     = make_float2(v[0], v[1]);
                *(float2*)&Cf[(size_t)(r+8)*N + c] = make_float2(v[2], v[3]);
            }
        }
    }
}

// ------------------------- qk-norm (q,k only) -> [B,NH,N,HD] fp16 -----------
__global__ void qknorm_kernel(const float* __restrict__ qn_w, const float* __restrict__ qn_b,
                              const float* __restrict__ kn_w, const float* __restrict__ kn_b) {
    int id = blockIdx.x * 8 + (threadIdx.x >> 5);
    if (id >= MROWS*32) return;
    int lane = threadIdx.x & 31;
    int r = id >> 5;
    int rem = id & 31;
    int w = rem >> 4;      // 0=q, 1=k
    int h = rem & 15;

    const __half* src = &g_qkvh[(size_t)r*3456 + w*1152 + h*72];
    float v0 = __half2float(src[lane]);
    float v1 = __half2float(src[lane + 32]);
    float v2 = (lane < 8) ? __half2float(src[lane + 64]) : 0.f;

    int b = r / SEQ, n = r % SEQ;
    __half* dst = (w == 0 ? g_qh : g_kh)
                 + (((size_t)(b*NHEAD + h)*SEQ + n)*HDIM);

    float s = v0 + v1 + v2;
    float ss = v0*v0 + v1*v1 + v2*v2;
    #pragma unroll
    for (int o = 16; o; o >>= 1) {
        s  += __shfl_xor_sync(0xffffffffu, s, o);
        ss += __shfl_xor_sync(0xffffffffu, ss, o);
    }
    float mean = s * (1.f/72.f);
    float var  = ss * (1.f/72.f) - mean*mean;
    float inv  = rsqrtf(var + 1e-5f);
    const float* ww = (w == 0) ? qn_w : kn_w;
    const float* wb = (w == 0) ? qn_b : kn_b;
    dst[lane]      = __float2half((v0 - mean)*inv*ww[lane]      + wb[lane]);
    dst[lane + 32] = __float2half((v1 - mean)*inv*ww[lane + 32] + wb[lane + 32]);
    if (lane < 8)
        dst[lane + 64] = __float2half((v2 - mean)*inv*ww[lane + 64] + wb[lane + 64]);
}

// ------------------------- V transpose: qkv v-slice -> [b][h][d][SEQ] -------
__global__ void __launch_bounds__(128) vtrans_kernel() {
    __shared__ uint32_t tile[64*37];   // stride 37 words = 74 halves
    int kt = blockIdx.x, h = blockIdx.y, b = blockIdx.z;
    int t = threadIdx.x;
    const uint32_t* src32 = (const uint32_t*)g_qkvh;

    for (int i = t; i < 64*36; i += 128) {
        int key = i / 36, w = i % 36;
        size_t off = ((size_t)(b*SEQ + kt*64 + key)*3456 + 2304 + h*72) / 2 + w;
        tile[key*37 + w] = src32[off];
    }
    __syncthreads();
    const __half* tileh = (const __half*)tile;
    uint32_t* dst32 = (uint32_t*)g_vth;
    for (int i = t; i < 72*32; i += 128) {
        int d = i / 32, w2 = i % 32;
        __half2 p;
        p.x = tileh[(2*w2)*74 + d];
        p.y = tileh[(2*w2 + 1)*74 + d];
        dst32[((size_t)((b*NHEAD + h)*HDIM + d)*SEQ)/2 + kt*32 + w2] = *(uint32_t*)&p;
    }
}

// ------------------------- fp16 tensor-core flash attention -----------------
#define AT_QW (128*36)
#define AT_KW (64*36)
#define AT_VW (72*36)
#define ATTN_SMEM ((AT_QW + 2*AT_KW + 2*AT_VW)*4)   // 57.6 KB

__global__ void __launch_bounds__(256) attn_h() {
    extern __shared__ uint32_t smw[];
    uint32_t* Qs = smw;
    uint32_t* Kb = Qs + AT_QW;
    uint32_t* Vb = Kb + 2*AT_KW;

    int b = blockIdx.z, h = blockIdx.y, q0 = blockIdx.x*128;
    int tid = threadIdx.x, lane = tid & 31, wid = tid >> 5;
    int lr = lane >> 2, lc = lane & 3;
    int wr = wid * 16;
    size_t base = (size_t)(b*NHEAD + h) * SEQ * HDIM;
    const __half* vbase = &g_vth[(size_t)(b*NHEAD + h) * HDIM * SEQ];
    const float scale = 0.11785113019775793f;

    auto load_stage = [&](int t, int buf) {
        const __half* kg = &g_kh[base + (size_t)(t*64)*HDIM];
        for (int i = tid; i < 576; i += 256) {
            int r = i / 9, c = i % 9;
            cp16(&Kb[buf*AT_KW + r*36 + c*4], kg + r*HDIM + c*8);
        }
        const __half* vg = vbase + t*64;
        for (int i = tid; i < 576; i += 256) {
            int d = i >> 3, c = i & 7;
            cp16(&Vb[buf*AT_VW + d*36 + c*4], vg + (size_t)d*SEQ + c*8);
        }
        asm volatile("cp.async.commit_group;");
    };

    {
        const uint4* qg = (const uint4*)&g_qh[base + (size_t)q0*HDIM];
        for (int i = tid; i < 128*9; i += 256) {
            int r = i / 9, c = i % 9;
            *(uint4*)&Qs[r*36 + c*4] = qg[i];
        }
    }
    load_stage(0, 0);

    float4 o[9];
    #pragma unroll
    for (int i = 0; i < 9; i++) o[i] = make_float4(0.f,0.f,0.f,0.f);
    float m_lo = -INFINITY, m_hi = -INFINITY, l_lo = 0.f, l_hi = 0.f;

    for (int t = 0; t < 16; t++) {
        asm volatile("cp.async.wait_group 0;");
        __syncthreads();
        if (t + 1 < 16) load_stage(t + 1, (t + 1) & 1);
        int buf = t & 1;
        const uint32_t* Ks = &Kb[buf*AT_KW];
        const uint32_t* Vt = &Vb[buf*AT_VW];

        float4 sc[8];
        #pragma unroll
        for (int i = 0; i < 8; i++) sc[i] = make_float4(0.f,0.f,0.f,0.f);
        #pragma unroll
        for (int k16 = 0; k16 < 4; k16++) {
            int kw = k16*8 + lc;
            uint32_t af[4];
            af[0] = Qs[(wr+lr)*36 + kw];
            af[1] = Qs[(wr+8+lr)*36 + kw];
            af[2] = Qs[(wr+lr)*36 + kw + 4];
            af[3] = Qs[(wr+8+lr)*36 + kw + 4];
            #pragma unroll
            for (int nj = 0; nj < 8; nj++) {
                int cc = nj*8 + lr;
                uint32_t bf[2] = {Ks[cc*36 + kw], Ks[cc*36 + kw + 4]};
                mma_f16(sc[nj], af, bf);
            }
        }
        {
            int kw = 32 + lc;
            uint32_t a0 = Qs[(wr+lr)*36 + kw];
            uint32_t a1 = Qs[(wr+8+lr)*36 + kw];
            #pragma unroll
            for (int nj = 0; nj < 8; nj++) {
                int cc = nj*8 + lr;
                mma_f16_k8(sc[nj], a0, a1, Ks[cc*36 + kw]);
            }
        }

        float tmax_lo = -INFINITY, tmax_hi = -INFINITY;
        #pragma unroll
        for (int nj = 0; nj < 8; nj++) {
            sc[nj].x *= scale; sc[nj].y *= scale; sc[nj].z *= scale; sc[nj].w *= scale;
            tmax_lo = fmaxf(tmax_lo, fmaxf(sc[nj].x, sc[nj].y));
            tmax_hi = fmaxf(tmax_hi, fmaxf(sc[nj].z, sc[nj].w));
        }
        tmax_lo = fmaxf(tmax_lo, __shfl_xor_sync(0xffffffffu, tmax_lo, 1));
        tmax_lo = fmaxf(tmax_lo, __shfl_xor_sync(0xffffffffu, tmax_lo, 2));
        tmax_hi = fmaxf(tmax_hi, __shfl_xor_sync(0xffffffffu, tmax_hi, 1));
        tmax_hi = fmaxf(tmax_hi, __shfl_xor_sync(0xffffffffu, tmax_hi, 2));

        float mn_lo = fmaxf(m_lo, tmax_lo);
        float mn_hi = fmaxf(m_hi, tmax_hi);
        float corr_lo = __expf(m_lo - mn_lo);
        float corr_hi = __expf(m_hi - mn_hi);
        l_lo *= corr_lo; l_hi *= corr_hi;
        #pragma unroll
        for (int i = 0; i < 9; i++) {
            o[i].x *= corr_lo; o[i].y *= corr_lo;
            o[i].z *= corr_hi; o[i].w *= corr_hi;
        }
        uint32_t ph[8][2];
        float sum_lo = 0.f, sum_hi = 0.f;
        #pragma unroll
        for (int nj = 0; nj < 8; nj++) {
            float px = __expf(sc[nj].x - mn_lo);
            float py = __expf(sc[nj].y - mn_lo);
            float pz = __expf(sc[nj].z - mn_hi);
            float pw = __expf(sc[nj].w - mn_hi);
            sum_lo += px + py; sum_hi += pz + pw;
            __half2 plo = __floats2half2_rn(px, py);
            __half2 phi = __floats2half2_rn(pz, pw);
            ph[nj][0] = *(uint32_t*)&plo;
            ph[nj][1] = *(uint32_t*)&phi;
        }
        sum_lo += __shfl_xor_sync(0xffffffffu, sum_lo, 1);
        sum_lo += __shfl_xor_sync(0xffffffffu, sum_lo, 2);
        sum_hi += __shfl_xor_sync(0xffffffffu, sum_hi, 1);
        sum_hi += __shfl_xor_sync(0xffffffffu, sum_hi, 2);
        l_lo += sum_lo; l_hi += sum_hi;
        m_lo = mn_lo; m_hi = mn_hi;

        #pragma unroll
        for (int k16 = 0; k16 < 4; k16++) {
            int kw = k16*8 + lc;
            uint32_t af[4];
            af[0] = ph[2*k16][0];
            af[1] = ph[2*k16][1];
            af[2] = ph[2*k16+1][0];
            af[3] = ph[2*k16+1][1];
            #pragma unroll
            for (int n9 = 0; n9 < 9; n9++) {
                int cc = n9*8 + lr;
                uint32_t bf[2] = {Vt[cc*36 + kw], Vt[cc*36 + kw + 4]};
                mma_f16(o[n9], af, bf);
            }
        }
    }

    float inv_lo = 1.f / l_lo, inv_hi = 1.f / l_hi;
    int r = b*SEQ + q0 + wr + lr;
    #pragma unroll
    for (int n9 = 0; n9 < 9; n9++) {
        int c = h*HDIM + n9*8 + 2*lc;
        __half2 p0 = __floats2half2_rn(o[n9].x*inv_lo, o[n9].y*inv_lo);
        __half2 p1 = __floats2half2_rn(o[n9].z*inv_hi, o[n9].w*inv_hi);
        *(__half2*)&g_oh[(size_t)r*HID + c]     = p0;
        *(__half2*)&g_oh[(size_t)(r+8)*HID + c] = p1;
    }
}

// ---------------------------------------------------------------------------
extern "C" void kernel_launch(void* const* d_in, const int* in_sizes, int n_in,
                              void* d_out, int out_size) {
    const float* x      = (const float*)d_in[0];
    const float* c      = (const float*)d_in[1];
    const float* w_ada  = (const float*)d_in[2];
    const float* b_ada  = (const float*)d_in[3];
    const float* w_qkv  = (const float*)d_in[4];
    const float* b_qkv  = (const float*)d_in[5];
    const float* qn_w   = (const float*)d_in[6];
    const float* qn_b   = (const float*)d_in[7];
    const float* kn_w   = (const float*)d_in[8];
    const float* kn_b   = (const float*)d_in[9];
    const float* w_proj = (const float*)d_in[10];
    const float* b_proj = (const float*)d_in[11];
    const float* w_fc1  = (const float*)d_in[12];
    const float* b_fc1  = (const float*)d_in[13];
    const float* w_fc2  = (const float*)d_in[14];
    const float* b_fc2  = (const float*)d_in[15];
    float* out = (float*)d_out;

    float *p_x1;
    __half *p_aih, *p_qkvh, *p_oh, *p_mih, *p_hh;
    __half *p_wqkt, *p_wpt, *p_wf1t, *p_wf2t;
    cudaGetSymbolAddress((void**)&p_x1,   g_x1);
    cudaGetSymbolAddress((void**)&p_aih,  g_aih);
    cudaGetSymbolAddress((void**)&p_qkvh, g_qkvh);
    cudaGetSymbolAddress((void**)&p_oh,   g_oh);
    cudaGetSymbolAddress((void**)&p_mih,  g_mih);
    cudaGetSymbolAddress((void**)&p_hh,   g_hh);
    cudaGetSymbolAddress((void**)&p_wqkt, g_wqkt);
    cudaGetSymbolAddress((void**)&p_wpt,  g_wpt);
    cudaGetSymbolAddress((void**)&p_wf1t, g_wf1t);
    cudaGetSymbolAddress((void**)&p_wf2t, g_wf2t);

    static int attr_set = 0;
    if (!attr_set) {
        cudaFuncSetAttribute(gemm_hf, cudaFuncAttributeMaxDynamicSharedMemorySize, GEMM_SMEM);
        cudaFuncSetAttribute(attn_h, cudaFuncAttributeMaxDynamicSharedMemorySize, ATTN_SMEM);
        attr_set = 1;
    }

    wtrans_kernel<<<dim3(HID/64, DFF/64), 256>>>(w_fc2, p_wf2t, DFF, HID);
    adaln_kernel<<<dim3(MOD6/256, BB), 256>>>(c, w_ada, b_ada);
    modulate_kernel<<<MROWS, 288>>>(x, nullptr, 0, 1, -1, nullptr, p_aih);
    wtrans_kernel<<<dim3(3*HID/64, HID/64), 256>>>(w_qkv, p_wqkt, HID, 3*HID);
    gemm_hf<<<dim3(3*HID/128, MROWS/128), 128, GEMM_SMEM>>>(p_aih, p_wqkt, b_qkv, p_qkvh,
                                                            MROWS, 3*HID, HID, 0, 1, nullptr, 0);
    qknorm_kernel<<<MROWS*32/8, 256>>>(qn_w, qn_b, kn_w, kn_b);
    vtrans_kernel<<<dim3(SEQ/64, NHEAD, BB), 128>>>();
    wtrans_kernel<<<dim3(HID/64, HID/64), 256>>>(w_proj, p_wpt, HID, HID);
    wtrans_kernel<<<dim3(DFF/64, HID/64), 256>>>(w_fc1, p_wf1t, HID, DFF);
    attn_h<<<dim3(SEQ/128, NHEAD, BB), 256, ATTN_SMEM>>>();
    // proj with fused residual: x1 = x + g_msa * (o @ w_proj + b)
    gemm_hf<<<dim3(HID/128, MROWS/128), 128, GEMM_SMEM>>>(p_oh, p_wpt, b_proj, p_x1,
                                                          MROWS, HID, HID, 0, 0, x, 2);
    modulate_kernel<<<MROWS, 288>>>(p_x1, nullptr, 3, 4, -1, nullptr, p_mih);
    gemm_hf<<<dim3(DFF/128, MROWS/128), 128, GEMM_SMEM>>>(p_mih, p_wf1t, b_fc1, p_hh,
                                                          MROWS, DFF, HID, 1, 1, nullptr, 0);
    gemm_hf<<<dim3(HID/128, MROWS/128), 128, GEMM_SMEM>>>(p_hh, p_wf2t, b_fc2, out,
                                                          MROWS, HID, DFF, 0, 0, p_x1, 5);
}